// round 12
// baseline (speedup 1.0000x reference)
#include <cuda_runtime.h>
#include <cuda_bf16.h>
#include <math.h>
#include <stdint.h>

#define B_   2
#define S_   2048
#define HID_ 2048
#define H_   16
#define KV_  8
#define D_   128
#define MROWS (B_ * S_)   // 4096

// ---------------------------------------------------------------------------
// Scratch (__device__ globals; allocation-free rule)
// ---------------------------------------------------------------------------
__device__ float g_q[(size_t)MROWS * H_ * D_];
__device__ float g_k[(size_t)MROWS * KV_ * D_];
__device__ float g_v[(size_t)MROWS * KV_ * D_];
__device__ __nv_bfloat16 g_qh2[(size_t)MROWS * H_ * D_];
__device__ __nv_bfloat16 g_ql2[(size_t)MROWS * H_ * D_];
__device__ __nv_bfloat16 g_kh2[(size_t)MROWS * KV_ * D_];
__device__ __nv_bfloat16 g_kl2[(size_t)MROWS * KV_ * D_];
__device__ __nv_bfloat16 g_vh2[(size_t)MROWS * KV_ * D_];
__device__ __nv_bfloat16 g_vl2[(size_t)MROWS * KV_ * D_];
__device__ __nv_bfloat16 g_xh[(size_t)MROWS * HID_];
__device__ __nv_bfloat16 g_xl[(size_t)MROWS * HID_];
__device__ __nv_bfloat16 g_qwh[(size_t)H_ * D_ * HID_];
__device__ __nv_bfloat16 g_qwl[(size_t)H_ * D_ * HID_];
__device__ __nv_bfloat16 g_kwh[(size_t)KV_ * D_ * HID_];
__device__ __nv_bfloat16 g_kwl[(size_t)KV_ * D_ * HID_];
__device__ __nv_bfloat16 g_vwh[(size_t)KV_ * D_ * HID_];
__device__ __nv_bfloat16 g_vwl[(size_t)KV_ * D_ * HID_];
__device__ __nv_bfloat16 g_owh[(size_t)HID_ * H_ * D_];
__device__ __nv_bfloat16 g_owl[(size_t)HID_ * H_ * D_];
__device__ __nv_bfloat16 g_ath[(size_t)MROWS * H_ * D_];
__device__ __nv_bfloat16 g_atl[(size_t)MROWS * H_ * D_];

// ---------------------------------------------------------------------------
// Helpers
// ---------------------------------------------------------------------------
__device__ __forceinline__ uint32_t smem_u32(const void* p) {
    uint32_t a;
    asm("{ .reg .u64 t; cvta.to.shared.u64 t, %1; cvt.u32.u64 %0, t; }"
        : "=r"(a) : "l"(p));
    return a;
}

__device__ __forceinline__ void cpasync16(uint32_t dst, const void* src) {
    asm volatile("cp.async.cg.shared.global [%0], [%1], 16;" :: "r"(dst), "l"(src));
}

#define LDSM_X4(r0, r1, r2, r3, addr)                                         \
    asm volatile("ldmatrix.sync.aligned.m8n8.x4.shared.b16 {%0,%1,%2,%3}, [%4];" \
                 : "=r"(r0), "=r"(r1), "=r"(r2), "=r"(r3) : "r"(addr))

#define LDSM_X4_T(r0, r1, r2, r3, addr)                                       \
    asm volatile("ldmatrix.sync.aligned.m8n8.x4.trans.shared.b16 {%0,%1,%2,%3}, [%4];" \
                 : "=r"(r0), "=r"(r1), "=r"(r2), "=r"(r3) : "r"(addr))

__device__ __forceinline__ void ldsm_x4(uint32_t& r0, uint32_t& r1,
                                        uint32_t& r2, uint32_t& r3, uint32_t addr) {
    LDSM_X4(r0, r1, r2, r3, addr);
}

__device__ __forceinline__ void mma_bf16(float* c, const uint32_t* a, const uint32_t* b) {
    asm volatile("mma.sync.aligned.m16n8k16.row.col.f32.bf16.bf16.f32 "
                 "{%0,%1,%2,%3}, {%4,%5,%6,%7}, {%8,%9}, {%0,%1,%2,%3};"
                 : "+f"(c[0]), "+f"(c[1]), "+f"(c[2]), "+f"(c[3])
                 : "r"(a[0]), "r"(a[1]), "r"(a[2]), "r"(a[3]),
                   "r"(b[0]), "r"(b[1]));
}
__device__ __forceinline__ void mma16816(float* c, const uint32_t* a,
                                         uint32_t b0, uint32_t b1) {
    asm volatile("mma.sync.aligned.m16n8k16.row.col.f32.bf16.bf16.f32 "
                 "{%0,%1,%2,%3}, {%4,%5,%6,%7}, {%8,%9}, {%0,%1,%2,%3};"
                 : "+f"(c[0]), "+f"(c[1]), "+f"(c[2]), "+f"(c[3])
                 : "r"(a[0]), "r"(a[1]), "r"(a[2]), "r"(a[3]), "r"(b0), "r"(b1));
}

// pack (a,b) fp32 -> bf16x2 hi and residual bf16x2 lo
__device__ __forceinline__ void pk(float a, float b, uint32_t& hi, uint32_t& lo) {
    __nv_bfloat16 ha = __float2bfloat16(a), hb = __float2bfloat16(b);
    __nv_bfloat16 la = __float2bfloat16(a - __bfloat162float(ha));
    __nv_bfloat16 lb = __float2bfloat16(b - __bfloat162float(hb));
    hi = ((uint32_t)*(uint16_t*)&hb << 16) | (uint32_t)*(uint16_t*)&ha;
    lo = ((uint32_t)*(uint16_t*)&lb << 16) | (uint32_t)*(uint16_t*)&la;
}

// ---------------------------------------------------------------------------
// split helper + fused 5-array split kernel (x, qw, kw, vw, ow), 2 elems/thread
// ---------------------------------------------------------------------------
__device__ __forceinline__ void split_store(float4 v, __nv_bfloat162* h,
                                            __nv_bfloat162* l, int i)
{
    __nv_bfloat16 hx = __float2bfloat16(v.x);
    __nv_bfloat16 hy = __float2bfloat16(v.y);
    __nv_bfloat16 hz = __float2bfloat16(v.z);
    __nv_bfloat16 hw = __float2bfloat16(v.w);
    __nv_bfloat16 lx = __float2bfloat16(v.x - __bfloat162float(hx));
    __nv_bfloat16 ly = __float2bfloat16(v.y - __bfloat162float(hy));
    __nv_bfloat16 lz = __float2bfloat16(v.z - __bfloat162float(hz));
    __nv_bfloat16 lw = __float2bfloat16(v.w - __bfloat162float(hw));
    h[2 * i]     = __nv_bfloat162(hx, hy);
    h[2 * i + 1] = __nv_bfloat162(hz, hw);
    l[2 * i]     = __nv_bfloat162(lx, ly);
    l[2 * i + 1] = __nv_bfloat162(lz, lw);
}
__device__ __forceinline__ void split1(const float4* __restrict__ s,
                                       __nv_bfloat162* __restrict__ h,
                                       __nv_bfloat162* __restrict__ l, int i)
{
    split_store(s[i], h, l, i);
}

#define NX4  (MROWS * HID_ / 4)        // 2097152
#define NQW4 (H_ * D_ * HID_ / 4)      // 1048576
#define NKW4 (KV_ * D_ * HID_ / 4)     // 524288
#define NSPLIT_TOT (NX4 + 2 * NQW4 + 2 * NKW4)   // 5242880

struct SplitTgt { const float4* s; __nv_bfloat162* h; __nv_bfloat162* l; int idx; };

__global__ __launch_bounds__(256) void split5(
    const float4* __restrict__ x,  const float4* __restrict__ qw,
    const float4* __restrict__ kw, const float4* __restrict__ vw,
    const float4* __restrict__ ow,
    __nv_bfloat162* xh, __nv_bfloat162* xl,
    __nv_bfloat162* qwh, __nv_bfloat162* qwl,
    __nv_bfloat162* kwh, __nv_bfloat162* kwl,
    __nv_bfloat162* vwh, __nv_bfloat162* vwl,
    __nv_bfloat162* owh, __nv_bfloat162* owl)
{
    auto resolve = [&](int i) -> SplitTgt {
        if (i < NX4) return {x, xh, xl, i};
        i -= NX4;
        if (i < NQW4) return {qw, qwh, qwl, i};
        i -= NQW4;
        if (i < NKW4) return {kw, kwh, kwl, i};
        i -= NKW4;
        if (i < NKW4) return {vw, vwh, vwl, i};
        i -= NKW4;
        return {ow, owh, owl, i};
    };
    int gid = blockIdx.x * 256 + threadIdx.x;
    SplitTgt t0 = resolve(2 * gid);
    SplitTgt t1 = resolve(2 * gid + 1);
    float4 a = t0.s[t0.idx];          // two independent loads (MLP=2)
    float4 b = t1.s[t1.idx];
    split_store(a, t0.h, t0.l, t0.idx);
    split_store(b, t1.h, t1.l, t1.idx);
}

// ---------------------------------------------------------------------------
// bf16x3 mma.sync GEMM body: C[m,n] = sum_k A[m,k]*B[n,k]
// 512 threads / 16 warps (4x4), warp tile 32x32 -> 2x warps/SM vs R11.
// ---------------------------------------------------------------------------
#define GK_      32
#define RSTR_B   80u
#define TILE_B   (128u * RSTR_B)
#define STAGE_B  (4u * TILE_B)
#define GEMM_SMEM (2 * 40960)

__device__ __forceinline__ void g_fill(
    uint32_t dst, const __nv_bfloat16* Ah, const __nv_bfloat16* Al,
    const __nv_bfloat16* Bh, const __nv_bfloat16* Bl,
    int m0, int n0, int K, int k0, int tid)
{
#pragma unroll
    for (int i = 0; i < 4; i++) {
        int idx = tid + i * 512;
        int t   = idx >> 9;
        int rem = idx & 511;
        int r   = rem >> 2;
        int seg = rem & 3;
        const __nv_bfloat16* src;
        if      (t == 0) src = Ah + (size_t)(m0 + r) * K + k0 + seg * 8;
        else if (t == 1) src = Al + (size_t)(m0 + r) * K + k0 + seg * 8;
        else if (t == 2) src = Bh + (size_t)(n0 + r) * K + k0 + seg * 8;
        else             src = Bl + (size_t)(n0 + r) * K + k0 + seg * 8;
        uint32_t d = dst + (uint32_t)t * TILE_B + (uint32_t)r * RSTR_B + (uint32_t)seg * 16u;
        cpasync16(d, src);
    }
}

__device__ __forceinline__ void gemm_body(
    const __nv_bfloat16* Ah, const __nv_bfloat16* Al,
    const __nv_bfloat16* Bh, const __nv_bfloat16* Bl,
    float* C, int N, int K, int m0, int n0, char* smem)
{
    const uint32_t sb  = smem_u32(smem);
    const int tid  = threadIdx.x;
    const int wid  = tid >> 5, lane = tid & 31;
    const int wm   = (wid >> 2) << 5;   // 0,32,64,96
    const int wn   = (wid & 3)  << 5;   // 0,32,64,96

    const uint32_t aoff = (uint32_t)(wm + (lane & 15)) * RSTR_B + (uint32_t)((lane >> 4) * 16);
    const uint32_t boff = (uint32_t)(wn + ((lane >> 4) << 3) + (lane & 7)) * RSTR_B
                        + (uint32_t)(((lane >> 3) & 1) * 16);

    float acc[2][4][4];
#pragma unroll
    for (int mi = 0; mi < 2; mi++)
#pragma unroll
        for (int ni = 0; ni < 4; ni++)
#pragma unroll
            for (int r = 0; r < 4; r++) acc[mi][ni][r] = 0.f;

    g_fill(sb, Ah, Al, Bh, Bl, m0, n0, K, 0, tid);
    asm volatile("cp.async.commit_group;");

    const int nit = K / GK_;
    for (int it = 0; it < nit; ++it) {
        const int cur = it & 1;
        if (it + 1 < nit) {
            g_fill(sb + (uint32_t)(cur ^ 1) * STAGE_B, Ah, Al, Bh, Bl,
                   m0, n0, K, (it + 1) * GK_, tid);
            asm volatile("cp.async.commit_group;");
            asm volatile("cp.async.wait_group 1;");
        } else {
            asm volatile("cp.async.wait_group 0;");
        }
        __syncthreads();

        const uint32_t stg = sb + (uint32_t)cur * STAGE_B;
        const uint32_t sAh = stg;
        const uint32_t sAl = stg + TILE_B;
        const uint32_t sBh = stg + 2u * TILE_B;
        const uint32_t sBl = stg + 3u * TILE_B;

#pragma unroll
        for (int kh = 0; kh < 2; kh++) {
            const uint32_t kb = (uint32_t)kh * 32u;
            uint32_t ah[2][4], al[2][4], bh[4][2], bl[4][2];
#pragma unroll
            for (int mi = 0; mi < 2; mi++) {
                ldsm_x4(ah[mi][0], ah[mi][1], ah[mi][2], ah[mi][3],
                        sAh + aoff + (uint32_t)(mi * 16) * RSTR_B + kb);
                ldsm_x4(al[mi][0], al[mi][1], al[mi][2], al[mi][3],
                        sAl + aoff + (uint32_t)(mi * 16) * RSTR_B + kb);
            }
#pragma unroll
            for (int nt = 0; nt < 2; nt++) {
                uint32_t r0, r1, r2, r3;
                ldsm_x4(r0, r1, r2, r3, sBh + boff + (uint32_t)(nt * 16) * RSTR_B + kb);
                bh[nt * 2 + 0][0] = r0; bh[nt * 2 + 0][1] = r1;
                bh[nt * 2 + 1][0] = r2; bh[nt * 2 + 1][1] = r3;
                ldsm_x4(r0, r1, r2, r3, sBl + boff + (uint32_t)(nt * 16) * RSTR_B + kb);
                bl[nt * 2 + 0][0] = r0; bl[nt * 2 + 0][1] = r1;
                bl[nt * 2 + 1][0] = r2; bl[nt * 2 + 1][1] = r3;
            }
#pragma unroll
            for (int mi = 0; mi < 2; mi++)
#pragma unroll
                for (int ni = 0; ni < 4; ni++) {
                    mma_bf16(acc[mi][ni], ah[mi], bh[ni]);
                    mma_bf16(acc[mi][ni], ah[mi], bl[ni]);
                    mma_bf16(acc[mi][ni], al[mi], bh[ni]);
                }
        }
        __syncthreads();
    }

#pragma unroll
    for (int mi = 0; mi < 2; mi++) {
        const int row = m0 + wm + mi * 16 + (lane >> 2);
#pragma unroll
        for (int ni = 0; ni < 4; ni++) {
            const int col = n0 + wn + ni * 8 + (lane & 3) * 2;
            *(float2*)&C[(size_t)row * N + col] =
                make_float2(acc[mi][ni][0], acc[mi][ni][1]);
            *(float2*)&C[(size_t)(row + 8) * N + col] =
                make_float2(acc[mi][ni][2], acc[mi][ni][3]);
        }
    }
}

__global__ __launch_bounds__(512, 1) void gemm_bf16x3(
    const __nv_bfloat16* __restrict__ Ah, const __nv_bfloat16* __restrict__ Al,
    const __nv_bfloat16* __restrict__ Bh, const __nv_bfloat16* __restrict__ Bl,
    float* __restrict__ C, int N, int K)
{
    extern __shared__ __align__(128) char smem[];
    gemm_body(Ah, Al, Bh, Bl, C, N, K, blockIdx.y << 7, blockIdx.x << 7, smem);
}

// Fused Q/K/V projection: one launch, per-block weight/output select.
__global__ __launch_bounds__(512, 1) void gemm_qkv(
    const __nv_bfloat16* __restrict__ xh, const __nv_bfloat16* __restrict__ xl,
    const __nv_bfloat16* __restrict__ qwh, const __nv_bfloat16* __restrict__ qwl,
    const __nv_bfloat16* __restrict__ kwh, const __nv_bfloat16* __restrict__ kwl,
    const __nv_bfloat16* __restrict__ vwh, const __nv_bfloat16* __restrict__ vwl,
    float* __restrict__ q, float* __restrict__ k, float* __restrict__ v, int K)
{
    extern __shared__ __align__(128) char smem[];
    const int bxx = blockIdx.x;
    const __nv_bfloat16 *Bh, *Bl;
    float* C; int N, n0;
    if (bxx < 16)      { Bh = qwh; Bl = qwl; C = q; N = 2048; n0 = bxx << 7; }
    else if (bxx < 24) { Bh = kwh; Bl = kwl; C = k; N = 1024; n0 = (bxx - 16) << 7; }
    else               { Bh = vwh; Bl = vwl; C = v; N = 1024; n0 = (bxx - 24) << 7; }
    gemm_body(xh, xl, Bh, Bl, C, N, K, blockIdx.y << 7, n0, smem);
}

// ---------------------------------------------------------------------------
// Fused prep: warp-per-row RMSNorm+RoPE (no smem/barriers) + V bf16 split.
// 128 threads/block. blocks: [0,16384) q | [16384,24576) k | [24576,28672) v
// ---------------------------------------------------------------------------
__device__ __forceinline__ void rms_rope_warp(
    const float* __restrict__ X, const float* __restrict__ pe,
    const float* __restrict__ w, int nheads, int row, int lane,
    __nv_bfloat16* __restrict__ Xh, __nv_bfloat16* __restrict__ Xl)
{
    const int bs = row / nheads;
    float4 v = *(const float4*)(X + (size_t)row * 128 + lane * 4);
    float ss = v.x * v.x + v.y * v.y + v.z * v.z + v.w * v.w;
#pragma unroll
    for (int o = 16; o > 0; o >>= 1) ss += __shfl_xor_sync(0xffffffffu, ss, o);
    float r = rsqrtf(ss * (1.f / 128.f) + 1e-6f);
    float4 wv = *(const float4*)(w + lane * 4);
    float xn[4] = {v.x * r * wv.x, v.y * r * wv.y, v.z * r * wv.z, v.w * r * wv.w};

    const int dbase = (lane & 15) * 4;
    float4 cv = *(const float4*)(pe + (size_t)bs * 128 + dbase);
    float4 sv = *(const float4*)(pe + (size_t)bs * 128 + 64 + dbase);
    float c[4] = {cv.x, cv.y, cv.z, cv.w};
    float s[4] = {sv.x, sv.y, sv.z, sv.w};
    float other[4];
#pragma unroll
    for (int j = 0; j < 4; j++) other[j] = __shfl_xor_sync(0xffffffffu, xn[j], 16);
    const bool low = (lane < 16);
    float out[4];
#pragma unroll
    for (int j = 0; j < 4; j++)
        out[j] = low ? (xn[j] * c[j] - other[j] * s[j])
                     : (other[j] * s[j] + xn[j] * c[j]);

    uint32_t h0, l0, h1, l1;
    pk(out[0], out[1], h0, l0);
    pk(out[2], out[3], h1, l1);
    *(uint2*)(Xh + (size_t)row * 128 + lane * 4) = make_uint2(h0, h1);
    *(uint2*)(Xl + (size_t)row * 128 + lane * 4) = make_uint2(l0, l1);
}

#define PREP_QB (MROWS * H_ / 4)              // 16384
#define PREP_KB (MROWS * KV_ / 4)             // 8192
#define PREP_VB (MROWS * KV_ * D_ / 4 / 256)  // 4096

__global__ __launch_bounds__(128) void prep_fused(
    const float* __restrict__ q, const float* __restrict__ k,
    const float* __restrict__ v, const float* __restrict__ pe,
    const float* __restrict__ qnw, const float* __restrict__ knw,
    __nv_bfloat16* qh, __nv_bfloat16* ql,
    __nv_bfloat16* kh, __nv_bfloat16* kl,
    __nv_bfloat16* vh, __nv_bfloat16* vl)
{
    const int bid = blockIdx.x;
    const int lane = threadIdx.x & 31, wrp = threadIdx.x >> 5;
    if (bid < PREP_QB) {
        rms_rope_warp(q, pe, qnw, H_, bid * 4 + wrp, lane, qh, ql);
    } else if (bid < PREP_QB + PREP_KB) {
        rms_rope_warp(k, pe, knw, KV_, (bid - PREP_QB) * 4 + wrp, lane, kh, kl);
    } else {
        int i = (bid - PREP_QB - PREP_KB) * 256 + threadIdx.x;
        const float4* v4 = (const float4*)v;
        float4 a = v4[i];
        float4 b = v4[i + 128];
        split_store(a, (__nv_bfloat162*)vh, (__nv_bfloat162*)vl, i);
        split_store(b, (__nv_bfloat162*)vh, (__nv_bfloat162*)vl, i + 128);
    }
}

// ---------------------------------------------------------------------------
// Flash attention on tensor cores (bf16x3 both matmuls), causal GQA.
// BR=64 (4 warps x 16 rows), BC=32, 3-stage KV ring, 2 CTAs/SM. (unchanged)
// ---------------------------------------------------------------------------
#define F2STR   272u
#define F2_KH   0u
#define F2_KL   8704u
#define F2_VH   17408u
#define F2_VL   26112u
#define F2_STG  34816u
#define FLASH3_SMEM (3 * 34816)   // 104448

__global__ __launch_bounds__(128, 2) void flash_mma(
    const __nv_bfloat16* __restrict__ Qh, const __nv_bfloat16* __restrict__ Ql,
    const __nv_bfloat16* __restrict__ Kh, const __nv_bfloat16* __restrict__ Kl,
    const __nv_bfloat16* __restrict__ Vh, const __nv_bfloat16* __restrict__ Vl,
    __nv_bfloat16* __restrict__ Oh, __nv_bfloat16* __restrict__ Ol)
{
    extern __shared__ __align__(16) char smem[];
    const uint32_t sb = smem_u32(smem);
    const int tid = threadIdx.x, lane = tid & 31, w = tid >> 5;
    const int bx = gridDim.x - 1 - blockIdx.x;
    const int h = blockIdx.y, b = blockIdx.z, kvh = h >> 1;
    const int g = lane >> 2, tg = lane & 3;
    const int ntiles = 2 * bx + 2;

    {
        const size_t qbase = (((size_t)b * S_ + (size_t)bx * 64) * H_ + h) * D_;
        const uint32_t qdst = sb + 2u * F2_STG;
#pragma unroll
        for (int i = 0; i < 8; i++) {
            int idx = tid + i * 128;
            int r = idx >> 4, seg = idx & 15;
            size_t src = qbase + (size_t)r * (H_ * D_) + seg * 8;
            uint32_t dst = qdst + (uint32_t)r * F2STR + (uint32_t)seg * 16u;
            cpasync16(dst,          Qh + src);
            cpasync16(dst + 17408u, Ql + src);
        }
    }
    asm volatile("cp.async.commit_group;");

    auto fillKV = [&](int stage, int kt) {
        const size_t kbase = (((size_t)b * S_ + (size_t)kt * 32) * KV_ + kvh) * D_;
        const uint32_t sdst = sb + (uint32_t)stage * F2_STG;
#pragma unroll
        for (int i = 0; i < 4; i++) {
            int idx = tid + i * 128;
            int r = idx >> 4, seg = idx & 15;
            size_t src = kbase + (size_t)r * (KV_ * D_) + seg * 8;
            uint32_t dst = sdst + (uint32_t)r * F2STR + (uint32_t)seg * 16u;
            cpasync16(dst + F2_KH, Kh + src);
            cpasync16(dst + F2_KL, Kl + src);
            cpasync16(dst + F2_VH, Vh + src);
            cpasync16(dst + F2_VL, Vl + src);
        }
        asm volatile("cp.async.commit_group;");
    };

    fillKV(0, 0);
    fillKV(1, 1);

    asm volatile("cp.async.wait_group 2;");
    __syncthreads();

    uint32_t qfh[8][4], qfl[8][4];
    {
        const uint32_t aQ = sb + 2u * F2_STG
                          + (uint32_t)(w * 16 + (lane & 15)) * F2STR
                          + (uint32_t)((lane >> 4) * 16);
#pragma unroll
        for (int kb = 0; kb < 8; kb++) {
            ldsm_x4(qfh[kb][0], qfh[kb][1], qfh[kb][2], qfh[kb][3], aQ + kb * 32);
            ldsm_x4(qfl[kb][0], qfl[kb][1], qfl[kb][2], qfl[kb][3],
                    aQ + 17408u + kb * 32);
        }
    }

    float o[16][4];
#pragma unroll
    for (int i = 0; i < 16; i++)
#pragma unroll
        for (int j = 0; j < 4; j++) o[i][j] = 0.f;
    float m0 = -1e30f, m1 = -1e30f, l0 = 0.f, l1 = 0.f;

    const int qr0 = bx * 64 + w * 16 + g;
    const float sca2 = 0.12751744f;

    int cur = 0;
    for (int kt = 0; kt < ntiles; kt++) {
        if (kt + 1 < ntiles) {
            asm volatile("cp.async.wait_group 1;");
        } else {
            asm volatile("cp.async.wait_group 0;");
        }
        __syncthreads();
        if (kt + 2 < ntiles) {
            int fs = cur + 2; if (fs >= 3) fs -= 3;
            fillKV(fs, kt + 2);
        }

        if (kt * 32 <= bx * 64 + w * 16 + 15) {
            const uint32_t stg = sb + (uint32_t)cur * F2_STG;
            const uint32_t bK  = stg + (uint32_t)((((lane >> 4) << 3) + (lane & 7)) * F2STR)
                               + (uint32_t)(((lane >> 3) & 1) * 16);

            float sc[4][4];
#pragma unroll
            for (int i = 0; i < 4; i++)
#pragma unroll
                for (int j = 0; j < 4; j++) sc[i][j] = 0.f;

#pragma unroll
            for (int kb = 0; kb < 8; kb++) {
#pragma unroll
                for (int nt = 0; nt < 2; nt++) {
                    uint32_t kh0, kh1, kh2, kh3, kl0, kl1, kl2, kl3;
                    ldsm_x4(kh0, kh1, kh2, kh3,
                            bK + F2_KH + (uint32_t)(nt * 16) * F2STR + kb * 32);
                    ldsm_x4(kl0, kl1, kl2, kl3,
                            bK + F2_KL + (uint32_t)(nt * 16) * F2STR + kb * 32);
                    mma16816(sc[2 * nt],     qfh[kb], kh0, kh1);
                    mma16816(sc[2 * nt],     qfh[kb], kl0, kl1);
                    mma16816(sc[2 * nt],     qfl[kb], kh0, kh1);
                    mma16816(sc[2 * nt + 1], qfh[kb], kh2, kh3);
                    mma16816(sc[2 * nt + 1], qfh[kb], kl2, kl3);
                    mma16816(sc[2 * nt + 1], qfl[kb], kh2, kh3);
                }
            }

            const bool maskt = (kt * 32 + 31 > bx * 64 + w * 16);
            const int row0 = qr0, row1 = qr0 + 8, cb = kt * 32;
#pragma unroll
            for (int nt = 0; nt < 4; nt++) {
                int c0 = cb + nt * 8 + tg * 2;
                float v0 = sc[nt][0] * sca2, v1 = sc[nt][1] * sca2;
                float v2 = sc[nt][2] * sca2, v3 = sc[nt][3] * sca2;
                if (maskt) {
                    if (c0     > row0) v0 = -1e30f;
                    if (c0 + 1 > row0) v1 = -1e30f;
                    if (c0     > row1) v2 = -1e30f;
                    if (c0 + 1 > row1) v3 = -1e30f;
                }
                sc[nt][0] = v0; sc[nt][1] = v1; sc[nt][2] = v2; sc[nt][3] = v3;
            }

            float mx0 = -1e30f, mx1 = -1e30f;
#pragma unroll
            for (int nt = 0; nt < 4; nt++) {
                mx0 = fmaxf(mx0, fmaxf(sc[nt][0], sc[nt][1]));
                mx1 = fmaxf(mx1, fmaxf(sc[nt][2], sc[nt][3]));
            }
            mx0 = fmaxf(mx0, __shfl_xor_sync(0xffffffffu, mx0, 1));
            mx0 = fmaxf(mx0, __shfl_xor_sync(0xffffffffu, mx0, 2));
            mx1 = fmaxf(mx1, __shfl_xor_sync(0xffffffffu, mx1, 1));
            mx1 = fmaxf(mx1, __shfl_xor_sync(0xffffffffu, mx1, 2));
            const float mn0 = fmaxf(m0, mx0), mn1 = fmaxf(m1, mx1);
            const float al0 = exp2f(m0 - mn0), al1 = exp2f(m1 - mn1);
            m0 = mn0; m1 = mn1;
#pragma unroll
            for (int nt = 0; nt < 16; nt++) {
                o[nt][0] *= al0; o[nt][1] *= al0;
                o[nt][2] *= al1; o[nt][3] *= al1;
            }

            float s0 = 0.f, s1 = 0.f;
#pragma unroll
            for (int j = 0; j < 2; j++) {
                float p00 = exp2f(sc[2 * j][0] - mn0);
                float p01 = exp2f(sc[2 * j][1] - mn0);
                float p02 = exp2f(sc[2 * j][2] - mn1);
                float p03 = exp2f(sc[2 * j][3] - mn1);
                float p10 = exp2f(sc[2 * j + 1][0] - mn0);
                float p11 = exp2f(sc[2 * j + 1][1] - mn0);
                float p12 = exp2f(sc[2 * j + 1][2] - mn1);
                float p13 = exp2f(sc[2 * j + 1][3] - mn1);
                s0 += (p00 + p01) + (p10 + p11);
                s1 += (p02 + p03) + (p12 + p13);

                uint32_t ph[4], pl[4];
                pk(p00, p01, ph[0], pl[0]);
                pk(p02, p03, ph[1], pl[1]);
                pk(p10, p11, ph[2], pl[2]);
                pk(p12, p13, ph[3], pl[3]);

                const uint32_t vrow = stg
                    + (uint32_t)((j * 16 + ((lane >> 3) & 1) * 8 + (lane & 7)) * F2STR)
                    + (uint32_t)((lane >> 4) * 16);
#pragma unroll
                for (int ntp = 0; ntp < 8; ntp++) {
                    uint32_t vh0, vh1, vh2, vh3, vl0, vl1, vl2, vl3;
                    LDSM_X4_T(vh0, vh1, vh2, vh3, vrow + F2_VH + ntp * 32);
                    LDSM_X4_T(vl0, vl1, vl2, vl3, vrow + F2_VL + ntp * 32);
                    mma16816(o[2 * ntp],     ph, vh0, vh1);
                    mma16816(o[2 * ntp],     ph, vl0, vl1);
                    mma16816(o[2 * ntp],     pl, vh0, vh1);
                    mma16816(o[2 * ntp + 1], ph, vh2, vh3);
                    mma16816(o[2 * ntp + 1], ph, vl2, vl3);
                    mma16816(o[2 * ntp + 1], pl, vh2, vh3);
                }
            }
            s0 += __shfl_xor_sync(0xffffffffu, s0, 1);
            s0 += __shfl_xor_sync(0xffffffffu, s0, 2);
            s1 += __shfl_xor_sync(0xffffffffu, s1, 1);
            s1 += __shfl_xor_sync(0xffffffffu, s1, 2);
            l0 = l0 * al0 + s0;
            l1 = l1 * al1 + s1;
        }
        if (++cur == 3) cur = 0;
    }

    const float i0 = 1.f / l0, i1 = 1.f / l1;
    const size_t o0 = (((size_t)b * S_ + (size_t)qr0) * H_ + h) * D_;
    const size_t o1 = o0 + (size_t)8 * (H_ * D_);
#pragma unroll
    for (int nt = 0; nt < 16; nt++) {
        const int col = nt * 8 + tg * 2;
        uint32_t hi, lo;
        pk(o[nt][0] * i0, o[nt][1] * i0, hi, lo);
        *(uint32_t*)&Oh[o0 + col] = hi;
        *(uint32_t*)&Ol[o0 + col] = lo;
        pk(o[nt][2] * i1, o[nt][3] * i1, hi, lo);
        *(uint32_t*)&Oh[o1 + col] = hi;
        *(uint32_t*)&Ol[o1 + col] = lo;
    }
}

// ---------------------------------------------------------------------------
extern "C" void kernel_launch(void* const* d_in, const int* in_sizes, int n_in,
                              void* d_out, int out_size)
{
    const float* x   = (const float*)d_in[0];
    const float* pe  = (const float*)d_in[1];
    const float* q_w = (const float*)d_in[2];
    const float* k_w = (const float*)d_in[3];
    const float* v_w = (const float*)d_in[4];
    const float* o_w = (const float*)d_in[5];
    const float* qnw = (const float*)d_in[6];
    const float* knw = (const float*)d_in[7];
    float* out = (float*)d_out;

    float *q, *k, *v;
    __nv_bfloat16 *qh, *ql, *kh, *kl, *vh, *vl;
    __nv_bfloat16 *xh, *xl, *qwh, *qwl, *kwh, *kwl, *vwh, *vwl, *owh, *owl, *ath, *atl;
    cudaGetSymbolAddress((void**)&q,   g_q);
    cudaGetSymbolAddress((void**)&k,   g_k);
    cudaGetSymbolAddress((void**)&v,   g_v);
    cudaGetSymbolAddress((void**)&qh,  g_qh2);
    cudaGetSymbolAddress((void**)&ql,  g_ql2);
    cudaGetSymbolAddress((void**)&kh,  g_kh2);
    cudaGetSymbolAddress((void**)&kl,  g_kl2);
    cudaGetSymbolAddress((void**)&vh,  g_vh2);
    cudaGetSymbolAddress((void**)&vl,  g_vl2);
    cudaGetSymbolAddress((void**)&xh,  g_xh);
    cudaGetSymbolAddress((void**)&xl,  g_xl);
    cudaGetSymbolAddress((void**)&qwh, g_qwh);
    cudaGetSymbolAddress((void**)&qwl, g_qwl);
    cudaGetSymbolAddress((void**)&kwh, g_kwh);
    cudaGetSymbolAddress((void**)&kwl, g_kwl);
    cudaGetSymbolAddress((void**)&vwh, g_vwh);
    cudaGetSymbolAddress((void**)&vwl, g_vwl);
    cudaGetSymbolAddress((void**)&owh, g_owh);
    cudaGetSymbolAddress((void**)&owl, g_owl);
    cudaGetSymbolAddress((void**)&ath, g_ath);
    cudaGetSymbolAddress((void**)&atl, g_atl);

    cudaFuncSetAttribute(gemm_bf16x3, cudaFuncAttributeMaxDynamicSharedMemorySize,
                         GEMM_SMEM);
    cudaFuncSetAttribute(gemm_qkv, cudaFuncAttributeMaxDynamicSharedMemorySize,
                         GEMM_SMEM);
    cudaFuncSetAttribute(flash_mma, cudaFuncAttributeMaxDynamicSharedMemorySize,
                         FLASH3_SMEM);

    // 1) fused bf16 hi/lo splits of x and all weights (one launch, MLP=2)
    split5<<<NSPLIT_TOT / 512, 256>>>(
        (const float4*)x, (const float4*)q_w, (const float4*)k_w,
        (const float4*)v_w, (const float4*)o_w,
        (__nv_bfloat162*)xh,  (__nv_bfloat162*)xl,
        (__nv_bfloat162*)qwh, (__nv_bfloat162*)qwl,
        (__nv_bfloat162*)kwh, (__nv_bfloat162*)kwl,
        (__nv_bfloat162*)vwh, (__nv_bfloat162*)vwl,
        (__nv_bfloat162*)owh, (__nv_bfloat162*)owl);

    // 2) fused Q/K/V projections (bf16x3 mma.sync, 512 threads / 16 warps)
    gemm_qkv<<<dim3(32, 32), 512, GEMM_SMEM>>>(xh, xl, qwh, qwl, kwh, kwl,
                                               vwh, vwl, q, k, v, HID_);

    // 3) fused prep: warp-per-row rms+rope(Q,K) + split(V)  (one launch)
    prep_fused<<<PREP_QB + PREP_KB + PREP_VB, 128>>>(
        q, k, v, pe, qnw, knw, qh, ql, kh, kl, vh, vl);

    // 4) causal GQA flash attention (2 CTAs/SM, BR=64, BC=32)
    flash_mma<<<dim3(S_ / 64, H_, B_), 128, FLASH3_SMEM>>>(
        qh, ql, kh, kl, vh, vl, ath, atl);

    // 5) output projection (bf16x3 mma.sync, 512 threads / 16 warps)
    gemm_bf16x3<<<dim3(16, 32), 512, GEMM_SMEM>>>(ath, atl, owh, owl, out, HID_, HID_);
}

// round 13
// speedup vs baseline: 1.4393x; 1.4393x over previous
#include <cuda_runtime.h>
#include <cuda_fp16.h>
#include <math.h>
#include <stdint.h>

#define B_   2
#define S_   2048
#define HID_ 2048
#define H_   16
#define KV_  8
#define D_   128
#define MROWS (B_ * S_)   // 4096

// ---------------------------------------------------------------------------
// Scratch (__device__ globals; allocation-free rule)
// ---------------------------------------------------------------------------
__device__ float g_q[(size_t)MROWS * H_ * D_];
__device__ float g_k[(size_t)MROWS * KV_ * D_];
__device__ float g_v[(size_t)MROWS * KV_ * D_];
__device__ __half g_x16[(size_t)MROWS * HID_];
__device__ __half g_qwh[(size_t)H_ * D_ * HID_];
__device__ __half g_qwl[(size_t)H_ * D_ * HID_];
__device__ __half g_kwh[(size_t)KV_ * D_ * HID_];
__device__ __half g_kwl[(size_t)KV_ * D_ * HID_];
__device__ __half g_vwh[(size_t)KV_ * D_ * HID_];
__device__ __half g_vwl[(size_t)KV_ * D_ * HID_];
__device__ __half g_owh[(size_t)HID_ * H_ * D_];
__device__ __half g_owl[(size_t)HID_ * H_ * D_];
__device__ __half g_q16[(size_t)MROWS * H_ * D_];
__device__ __half g_kh16[(size_t)MROWS * KV_ * D_];
__device__ __half g_kl16[(size_t)MROWS * KV_ * D_];
__device__ __half g_vh16[(size_t)MROWS * KV_ * D_];
__device__ __half g_vl16[(size_t)MROWS * KV_ * D_];
__device__ __half g_at16[(size_t)MROWS * H_ * D_];

// ---------------------------------------------------------------------------
// Helpers
// ---------------------------------------------------------------------------
__device__ __forceinline__ uint32_t smem_u32(const void* p) {
    uint32_t a;
    asm("{ .reg .u64 t; cvta.to.shared.u64 t, %1; cvt.u32.u64 %0, t; }"
        : "=r"(a) : "l"(p));
    return a;
}

__device__ __forceinline__ void cpasync16(uint32_t dst, const void* src) {
    asm volatile("cp.async.cg.shared.global [%0], [%1], 16;" :: "r"(dst), "l"(src));
}

#define LDSM_X4(r0, r1, r2, r3, addr)                                         \
    asm volatile("ldmatrix.sync.aligned.m8n8.x4.shared.b16 {%0,%1,%2,%3}, [%4];" \
                 : "=r"(r0), "=r"(r1), "=r"(r2), "=r"(r3) : "r"(addr))

#define LDSM_X4_T(r0, r1, r2, r3, addr)                                       \
    asm volatile("ldmatrix.sync.aligned.m8n8.x4.trans.shared.b16 {%0,%1,%2,%3}, [%4];" \
                 : "=r"(r0), "=r"(r1), "=r"(r2), "=r"(r3) : "r"(addr))

__device__ __forceinline__ void ldsm_x4(uint32_t& r0, uint32_t& r1,
                                        uint32_t& r2, uint32_t& r3, uint32_t addr) {
    LDSM_X4(r0, r1, r2, r3, addr);
}

// fp16 mma, fp32 accum
__device__ __forceinline__ void mma_h(float* c, const uint32_t* a,
                                      uint32_t b0, uint32_t b1) {
    asm volatile("mma.sync.aligned.m16n8k16.row.col.f32.f16.f16.f32 "
                 "{%0,%1,%2,%3}, {%4,%5,%6,%7}, {%8,%9}, {%0,%1,%2,%3};"
                 : "+f"(c[0]), "+f"(c[1]), "+f"(c[2]), "+f"(c[3])
                 : "r"(a[0]), "r"(a[1]), "r"(a[2]), "r"(a[3]), "r"(b0), "r"(b1));
}

__device__ __forceinline__ uint32_t pkh(float a, float b) {
    __half2 h = __floats2half2_rn(a, b);
    return *(uint32_t*)&h;
}
__device__ __forceinline__ void pkhl(float a, float b, uint32_t& hi, uint32_t& lo) {
    __half ha = __float2half_rn(a), hb = __float2half_rn(b);
    __half la = __float2half_rn(a - __half2float(ha));
    __half lb = __float2half_rn(b - __half2float(hb));
    hi = ((uint32_t)*(uint16_t*)&hb << 16) | (uint32_t)*(uint16_t*)&ha;
    lo = ((uint32_t)*(uint16_t*)&lb << 16) | (uint32_t)*(uint16_t*)&la;
}

// ---------------------------------------------------------------------------
// Fused split kernel: x -> single fp16; weights -> fp16 hi/lo.
// ---------------------------------------------------------------------------
#define NX4  (MROWS * HID_ / 4)        // 2097152
#define NQW4 (H_ * D_ * HID_ / 4)      // 1048576
#define NKW4 (KV_ * D_ * HID_ / 4)     // 524288
#define NSPLIT_TOT (NX4 + 2 * NQW4 + 2 * NKW4)   // 5242880

__device__ __forceinline__ void cvt_single(float4 v, __half* o16, int i) {
    uint2 p = make_uint2(pkh(v.x, v.y), pkh(v.z, v.w));
    *(uint2*)(o16 + 4 * (size_t)i) = p;
}
__device__ __forceinline__ void split_hl(float4 v, __half* h, __half* l, int i) {
    uint32_t h0, l0, h1, l1;
    pkhl(v.x, v.y, h0, l0);
    pkhl(v.z, v.w, h1, l1);
    *(uint2*)(h + 4 * (size_t)i) = make_uint2(h0, h1);
    *(uint2*)(l + 4 * (size_t)i) = make_uint2(l0, l1);
}

__global__ __launch_bounds__(256) void split5(
    const float4* __restrict__ x,  const float4* __restrict__ qw,
    const float4* __restrict__ kw, const float4* __restrict__ vw,
    const float4* __restrict__ ow,
    __half* x16,
    __half* qwh, __half* qwl, __half* kwh, __half* kwl,
    __half* vwh, __half* vwl, __half* owh, __half* owl)
{
    auto proc = [&](int i) {
        if (i < NX4) { cvt_single(x[i], x16, i); return; }
        i -= NX4;
        if (i < NQW4) { split_hl(qw[i], qwh, qwl, i); return; }
        i -= NQW4;
        if (i < NKW4) { split_hl(kw[i], kwh, kwl, i); return; }
        i -= NKW4;
        if (i < NKW4) { split_hl(vw[i], vwh, vwl, i); return; }
        i -= NKW4;
        split_hl(ow[i], owh, owl, i);
    };
    int gid = blockIdx.x * 256 + threadIdx.x;
    proc(2 * gid);
    proc(2 * gid + 1);
}

// ---------------------------------------------------------------------------
// fp16x2 mma.sync GEMM: C[m,n] = sum_k A[m,k]*B[n,k], A single, B hi/lo.
// 256 threads / 8 warps (2x4), warp tile 64x32 (validated R5-R11 geometry).
// stage = A tile + Bh tile + Bl tile, each 128 rows x 32 half, stride 80B.
// ---------------------------------------------------------------------------
#define GK_      32
#define RSTR_B   80u
#define TILE_B   (128u * RSTR_B)
#define STAGE_B2 (3u * TILE_B)        // 30720
#define GEMM_SMEM (2 * 30720)

__device__ __forceinline__ void g_fill2(
    uint32_t dst, const __half* A16, const __half* Bh, const __half* Bl,
    int m0, int n0, int K, int k0, int tid)
{
#pragma unroll
    for (int i = 0; i < 6; i++) {
        int idx = tid + i * 256;
        int t   = idx >> 9;          // 0:A 1:Bh 2:Bl
        int rem = idx & 511;
        int r   = rem >> 2;
        int seg = rem & 3;
        const __half* src;
        if      (t == 0) src = A16 + (size_t)(m0 + r) * K + k0 + seg * 8;
        else if (t == 1) src = Bh  + (size_t)(n0 + r) * K + k0 + seg * 8;
        else             src = Bl  + (size_t)(n0 + r) * K + k0 + seg * 8;
        uint32_t d = dst + (uint32_t)t * TILE_B + (uint32_t)r * RSTR_B + (uint32_t)seg * 16u;
        cpasync16(d, src);
    }
}

__device__ __forceinline__ void gemm_body(
    const __half* A16, const __half* Bh, const __half* Bl,
    float* C, int N, int K, int m0, int n0, char* smem)
{
    const uint32_t sb  = smem_u32(smem);
    const int tid  = threadIdx.x;
    const int wid  = tid >> 5, lane = tid & 31;
    const int wm   = (wid >> 2) << 6;   // 0 or 64
    const int wn   = (wid & 3)  << 5;   // 0,32,64,96

    const uint32_t aoff = (uint32_t)(wm + (lane & 15)) * RSTR_B + (uint32_t)((lane >> 4) * 16);
    const uint32_t boff = (uint32_t)(wn + ((lane >> 4) << 3) + (lane & 7)) * RSTR_B
                        + (uint32_t)(((lane >> 3) & 1) * 16);

    float acc[4][4][4];
#pragma unroll
    for (int mi = 0; mi < 4; mi++)
#pragma unroll
        for (int ni = 0; ni < 4; ni++)
#pragma unroll
            for (int r = 0; r < 4; r++) acc[mi][ni][r] = 0.f;

    g_fill2(sb, A16, Bh, Bl, m0, n0, K, 0, tid);
    asm volatile("cp.async.commit_group;");

    const int nit = K / GK_;
    for (int it = 0; it < nit; ++it) {
        const int cur = it & 1;
        if (it + 1 < nit) {
            g_fill2(sb + (uint32_t)(cur ^ 1) * STAGE_B2, A16, Bh, Bl,
                    m0, n0, K, (it + 1) * GK_, tid);
            asm volatile("cp.async.commit_group;");
            asm volatile("cp.async.wait_group 1;");
        } else {
            asm volatile("cp.async.wait_group 0;");
        }
        __syncthreads();

        const uint32_t stg = sb + (uint32_t)cur * STAGE_B2;
        const uint32_t sA  = stg;
        const uint32_t sBh = stg + TILE_B;
        const uint32_t sBl = stg + 2u * TILE_B;

#pragma unroll
        for (int kh = 0; kh < 2; kh++) {
            const uint32_t kb = (uint32_t)kh * 32u;
            uint32_t ah[4][4], bh[4][2], bl[4][2];
#pragma unroll
            for (int mi = 0; mi < 4; mi++)
                ldsm_x4(ah[mi][0], ah[mi][1], ah[mi][2], ah[mi][3],
                        sA + aoff + (uint32_t)(mi * 16) * RSTR_B + kb);
#pragma unroll
            for (int nt = 0; nt < 2; nt++) {
                uint32_t r0, r1, r2, r3;
                ldsm_x4(r0, r1, r2, r3, sBh + boff + (uint32_t)(nt * 16) * RSTR_B + kb);
                bh[nt * 2 + 0][0] = r0; bh[nt * 2 + 0][1] = r1;
                bh[nt * 2 + 1][0] = r2; bh[nt * 2 + 1][1] = r3;
                ldsm_x4(r0, r1, r2, r3, sBl + boff + (uint32_t)(nt * 16) * RSTR_B + kb);
                bl[nt * 2 + 0][0] = r0; bl[nt * 2 + 0][1] = r1;
                bl[nt * 2 + 1][0] = r2; bl[nt * 2 + 1][1] = r3;
            }
#pragma unroll
            for (int mi = 0; mi < 4; mi++)
#pragma unroll
                for (int ni = 0; ni < 4; ni++) {
                    mma_h(acc[mi][ni], ah[mi], bh[ni][0], bh[ni][1]);
                    mma_h(acc[mi][ni], ah[mi], bl[ni][0], bl[ni][1]);
                }
        }
        __syncthreads();
    }

#pragma unroll
    for (int mi = 0; mi < 4; mi++) {
        const int row = m0 + wm + mi * 16 + (lane >> 2);
#pragma unroll
        for (int ni = 0; ni < 4; ni++) {
            const int col = n0 + wn + ni * 8 + (lane & 3) * 2;
            *(float2*)&C[(size_t)row * N + col] =
                make_float2(acc[mi][ni][0], acc[mi][ni][1]);
            *(float2*)&C[(size_t)(row + 8) * N + col] =
                make_float2(acc[mi][ni][2], acc[mi][ni][3]);
        }
    }
}

__global__ __launch_bounds__(256, 1) void gemm_fp16x2(
    const __half* __restrict__ A16, const __half* __restrict__ Bh,
    const __half* __restrict__ Bl, float* __restrict__ C, int N, int K)
{
    extern __shared__ __align__(128) char smem[];
    gemm_body(A16, Bh, Bl, C, N, K, blockIdx.y << 7, blockIdx.x << 7, smem);
}

// Fused Q/K/V projection: one launch, per-block weight/output select.
__global__ __launch_bounds__(256, 1) void gemm_qkv(
    const __half* __restrict__ x16,
    const __half* __restrict__ qwh, const __half* __restrict__ qwl,
    const __half* __restrict__ kwh, const __half* __restrict__ kwl,
    const __half* __restrict__ vwh, const __half* __restrict__ vwl,
    float* __restrict__ q, float* __restrict__ k, float* __restrict__ v, int K)
{
    extern __shared__ __align__(128) char smem[];
    const int bxx = blockIdx.x;
    const __half *Bh, *Bl;
    float* C; int N, n0;
    if (bxx < 16)      { Bh = qwh; Bl = qwl; C = q; N = 2048; n0 = bxx << 7; }
    else if (bxx < 24) { Bh = kwh; Bl = kwl; C = k; N = 1024; n0 = (bxx - 16) << 7; }
    else               { Bh = vwh; Bl = vwl; C = v; N = 1024; n0 = (bxx - 24) << 7; }
    gemm_body(x16, Bh, Bl, C, N, K, blockIdx.y << 7, n0, smem);
}

// ---------------------------------------------------------------------------
// Fused prep: warp-per-row RMSNorm+RoPE. Q -> single fp16; K -> fp16 hi/lo;
// V -> fp16 hi/lo split. 128 threads/block.
// ---------------------------------------------------------------------------
template <bool SPLIT>
__device__ __forceinline__ void rms_rope_warp(
    const float* __restrict__ X, const float* __restrict__ pe,
    const float* __restrict__ w, int nheads, int row, int lane,
    __half* __restrict__ Xh, __half* __restrict__ Xl)
{
    const int bs = row / nheads;
    float4 v = *(const float4*)(X + (size_t)row * 128 + lane * 4);
    float ss = v.x * v.x + v.y * v.y + v.z * v.z + v.w * v.w;
#pragma unroll
    for (int o = 16; o > 0; o >>= 1) ss += __shfl_xor_sync(0xffffffffu, ss, o);
    float r = rsqrtf(ss * (1.f / 128.f) + 1e-6f);
    float4 wv = *(const float4*)(w + lane * 4);
    float xn[4] = {v.x * r * wv.x, v.y * r * wv.y, v.z * r * wv.z, v.w * r * wv.w};

    const int dbase = (lane & 15) * 4;
    float4 cv = *(const float4*)(pe + (size_t)bs * 128 + dbase);
    float4 sv = *(const float4*)(pe + (size_t)bs * 128 + 64 + dbase);
    float c[4] = {cv.x, cv.y, cv.z, cv.w};
    float s[4] = {sv.x, sv.y, sv.z, sv.w};
    float other[4];
#pragma unroll
    for (int j = 0; j < 4; j++) other[j] = __shfl_xor_sync(0xffffffffu, xn[j], 16);
    const bool low = (lane < 16);
    float out[4];
#pragma unroll
    for (int j = 0; j < 4; j++)
        out[j] = low ? (xn[j] * c[j] - other[j] * s[j])
                     : (other[j] * s[j] + xn[j] * c[j]);

    if (SPLIT) {
        uint32_t h0, l0, h1, l1;
        pkhl(out[0], out[1], h0, l0);
        pkhl(out[2], out[3], h1, l1);
        *(uint2*)(Xh + (size_t)row * 128 + lane * 4) = make_uint2(h0, h1);
        *(uint2*)(Xl + (size_t)row * 128 + lane * 4) = make_uint2(l0, l1);
    } else {
        *(uint2*)(Xh + (size_t)row * 128 + lane * 4) =
            make_uint2(pkh(out[0], out[1]), pkh(out[2], out[3]));
    }
}

#define PREP_QB (MROWS * H_ / 4)              // 16384
#define PREP_KB (MROWS * KV_ / 4)             // 8192
#define PREP_VB (MROWS * KV_ * D_ / 4 / 256)  // 4096

__global__ __launch_bounds__(128) void prep_fused(
    const float* __restrict__ q, const float* __restrict__ k,
    const float* __restrict__ v, const float* __restrict__ pe,
    const float* __restrict__ qnw, const float* __restrict__ knw,
    __half* q16, __half* kh, __half* kl, __half* vh, __half* vl)
{
    const int bid = blockIdx.x;
    const int lane = threadIdx.x & 31, wrp = threadIdx.x >> 5;
    if (bid < PREP_QB) {
        rms_rope_warp<false>(q, pe, qnw, H_, bid * 4 + wrp, lane, q16, nullptr);
    } else if (bid < PREP_QB + PREP_KB) {
        rms_rope_warp<true>(k, pe, knw, KV_, (bid - PREP_QB) * 4 + wrp, lane, kh, kl);
    } else {
        int i = (bid - PREP_QB - PREP_KB) * 256 + threadIdx.x;
        const float4* v4 = (const float4*)v;
        float4 a = v4[i];
        float4 b = v4[i + 128];
        split_hl(a, vh, vl, i);
        split_hl(b, vh, vl, i + 128);
    }
}

// ---------------------------------------------------------------------------
// Flash attention, fp16x2 (Q/P single, K/V hi/lo), causal GQA.
// BR=64 (4 warps x 16 rows), BC=32, 3-stage KV ring, 2 CTAs/SM.
// ---------------------------------------------------------------------------
#define F2STR   272u
#define F2_KH   0u
#define F2_KL   8704u
#define F2_VH   17408u
#define F2_VL   26112u
#define F2_STG  34816u
#define FLASH3_SMEM (3 * 34816)   // 104448

__global__ __launch_bounds__(128, 2) void flash_mma(
    const __half* __restrict__ Q16,
    const __half* __restrict__ Kh, const __half* __restrict__ Kl,
    const __half* __restrict__ Vh, const __half* __restrict__ Vl,
    __half* __restrict__ Oa)
{
    extern __shared__ __align__(16) char smem[];
    const uint32_t sb = smem_u32(smem);
    const int tid = threadIdx.x, lane = tid & 31, w = tid >> 5;
    const int bx = gridDim.x - 1 - blockIdx.x;   // heavy diagonals first
    const int h = blockIdx.y, b = blockIdx.z, kvh = h >> 1;
    const int g = lane >> 2, tg = lane & 3;
    const int ntiles = 2 * bx + 2;               // >= 2

    // ---- prologue: cp.async Q (64 rows x 128 half, single) into stage-2 ----
    {
        const size_t qbase = (((size_t)b * S_ + (size_t)bx * 64) * H_ + h) * D_;
        const uint32_t qdst = sb + 2u * F2_STG;
#pragma unroll
        for (int i = 0; i < 8; i++) {
            int idx = tid + i * 128;
            int r = idx >> 4, seg = idx & 15;
            size_t src = qbase + (size_t)r * (H_ * D_) + seg * 8;
            cpasync16(qdst + (uint32_t)r * F2STR + (uint32_t)seg * 16u, Q16 + src);
        }
    }
    asm volatile("cp.async.commit_group;");

    auto fillKV = [&](int stage, int kt) {
        const size_t kbase = (((size_t)b * S_ + (size_t)kt * 32) * KV_ + kvh) * D_;
        const uint32_t sdst = sb + (uint32_t)stage * F2_STG;
#pragma unroll
        for (int i = 0; i < 4; i++) {
            int idx = tid + i * 128;
            int r = idx >> 4, seg = idx & 15;
            size_t src = kbase + (size_t)r * (KV_ * D_) + seg * 8;
            uint32_t dst = sdst + (uint32_t)r * F2STR + (uint32_t)seg * 16u;
            cpasync16(dst + F2_KH, Kh + src);
            cpasync16(dst + F2_KL, Kl + src);
            cpasync16(dst + F2_VH, Vh + src);
            cpasync16(dst + F2_VL, Vl + src);
        }
        asm volatile("cp.async.commit_group;");
    };

    fillKV(0, 0);
    fillKV(1, 1);

    asm volatile("cp.async.wait_group 2;");   // Q complete (own portions)
    __syncthreads();                          // all portions visible

    // ---- Q fragments -> registers (single fp16) ----
    uint32_t qf[8][4];
    {
        const uint32_t aQ = sb + 2u * F2_STG
                          + (uint32_t)(w * 16 + (lane & 15)) * F2STR
                          + (uint32_t)((lane >> 4) * 16);
#pragma unroll
        for (int kb = 0; kb < 8; kb++)
            ldsm_x4(qf[kb][0], qf[kb][1], qf[kb][2], qf[kb][3], aQ + kb * 32);
    }

    float o[16][4];
#pragma unroll
    for (int i = 0; i < 16; i++)
#pragma unroll
        for (int j = 0; j < 4; j++) o[i][j] = 0.f;
    float m0 = -1e30f, m1 = -1e30f, l0 = 0.f, l1 = 0.f;

    const int qr0 = bx * 64 + w * 16 + g;
    const float sca2 = 0.12751744f;   // log2(e)/sqrt(128)

    int cur = 0;
    for (int kt = 0; kt < ntiles; kt++) {
        if (kt + 1 < ntiles) {
            asm volatile("cp.async.wait_group 1;");
        } else {
            asm volatile("cp.async.wait_group 0;");
        }
        __syncthreads();
        if (kt + 2 < ntiles) {
            int fs = cur + 2; if (fs >= 3) fs -= 3;
            fillKV(fs, kt + 2);
        }

        if (kt * 32 <= bx * 64 + w * 16 + 15) {
            const uint32_t stg = sb + (uint32_t)cur * F2_STG;
            const uint32_t bK  = stg + (uint32_t)((((lane >> 4) << 3) + (lane & 7)) * F2STR)
                               + (uint32_t)(((lane >> 3) & 1) * 16);

            // ---- S = Q (Kh + Kl), 2 products ----
            float sc[4][4];
#pragma unroll
            for (int i = 0; i < 4; i++)
#pragma unroll
                for (int j = 0; j < 4; j++) sc[i][j] = 0.f;

#pragma unroll
            for (int kb = 0; kb < 8; kb++) {
#pragma unroll
                for (int nt = 0; nt < 2; nt++) {
                    uint32_t kh0, kh1, kh2, kh3, kl0, kl1, kl2, kl3;
                    ldsm_x4(kh0, kh1, kh2, kh3,
                            bK + F2_KH + (uint32_t)(nt * 16) * F2STR + kb * 32);
                    ldsm_x4(kl0, kl1, kl2, kl3,
                            bK + F2_KL + (uint32_t)(nt * 16) * F2STR + kb * 32);
                    mma_h(sc[2 * nt],     qf[kb], kh0, kh1);
                    mma_h(sc[2 * nt],     qf[kb], kl0, kl1);
                    mma_h(sc[2 * nt + 1], qf[kb], kh2, kh3);
                    mma_h(sc[2 * nt + 1], qf[kb], kl2, kl3);
                }
            }

            // ---- scale (log2 domain) + causal mask ----
            const bool maskt = (kt * 32 + 31 > bx * 64 + w * 16);
            const int row0 = qr0, row1 = qr0 + 8, cb = kt * 32;
#pragma unroll
            for (int nt = 0; nt < 4; nt++) {
                int c0 = cb + nt * 8 + tg * 2;
                float v0 = sc[nt][0] * sca2, v1 = sc[nt][1] * sca2;
                float v2 = sc[nt][2] * sca2, v3 = sc[nt][3] * sca2;
                if (maskt) {
                    if (c0     > row0) v0 = -1e30f;
                    if (c0 + 1 > row0) v1 = -1e30f;
                    if (c0     > row1) v2 = -1e30f;
                    if (c0 + 1 > row1) v3 = -1e30f;
                }
                sc[nt][0] = v0; sc[nt][1] = v1; sc[nt][2] = v2; sc[nt][3] = v3;
            }

            // ---- row max ----
            float mx0 = -1e30f, mx1 = -1e30f;
#pragma unroll
            for (int nt = 0; nt < 4; nt++) {
                mx0 = fmaxf(mx0, fmaxf(sc[nt][0], sc[nt][1]));
                mx1 = fmaxf(mx1, fmaxf(sc[nt][2], sc[nt][3]));
            }
            mx0 = fmaxf(mx0, __shfl_xor_sync(0xffffffffu, mx0, 1));
            mx0 = fmaxf(mx0, __shfl_xor_sync(0xffffffffu, mx0, 2));
            mx1 = fmaxf(mx1, __shfl_xor_sync(0xffffffffu, mx1, 1));
            mx1 = fmaxf(mx1, __shfl_xor_sync(0xffffffffu, mx1, 2));
            const float mn0 = fmaxf(m0, mx0), mn1 = fmaxf(m1, mx1);
            const float al0 = exp2f(m0 - mn0), al1 = exp2f(m1 - mn1);
            m0 = mn0; m1 = mn1;
#pragma unroll
            for (int nt = 0; nt < 16; nt++) {
                o[nt][0] *= al0; o[nt][1] *= al0;
                o[nt][2] *= al1; o[nt][3] *= al1;
            }

            // ---- per-slice (2 x k16): exp2 -> pack (single) -> PV ----
            float s0 = 0.f, s1 = 0.f;
#pragma unroll
            for (int j = 0; j < 2; j++) {
                float p00 = exp2f(sc[2 * j][0] - mn0);
                float p01 = exp2f(sc[2 * j][1] - mn0);
                float p02 = exp2f(sc[2 * j][2] - mn1);
                float p03 = exp2f(sc[2 * j][3] - mn1);
                float p10 = exp2f(sc[2 * j + 1][0] - mn0);
                float p11 = exp2f(sc[2 * j + 1][1] - mn0);
                float p12 = exp2f(sc[2 * j + 1][2] - mn1);
                float p13 = exp2f(sc[2 * j + 1][3] - mn1);
                s0 += (p00 + p01) + (p10 + p11);
                s1 += (p02 + p03) + (p12 + p13);

                uint32_t ph[4];
                ph[0] = pkh(p00, p01);
                ph[1] = pkh(p02, p03);
                ph[2] = pkh(p10, p11);
                ph[3] = pkh(p12, p13);

                const uint32_t vrow = stg
                    + (uint32_t)((j * 16 + ((lane >> 3) & 1) * 8 + (lane & 7)) * F2STR)
                    + (uint32_t)((lane >> 4) * 16);
#pragma unroll
                for (int ntp = 0; ntp < 8; ntp++) {
                    uint32_t vh0, vh1, vh2, vh3, vl0, vl1, vl2, vl3;
                    LDSM_X4_T(vh0, vh1, vh2, vh3, vrow + F2_VH + ntp * 32);
                    LDSM_X4_T(vl0, vl1, vl2, vl3, vrow + F2_VL + ntp * 32);
                    mma_h(o[2 * ntp],     ph, vh0, vh1);
                    mma_h(o[2 * ntp],     ph, vl0, vl1);
                    mma_h(o[2 * ntp + 1], ph, vh2, vh3);
                    mma_h(o[2 * ntp + 1], ph, vl2, vl3);
                }
            }
            s0 += __shfl_xor_sync(0xffffffffu, s0, 1);
            s0 += __shfl_xor_sync(0xffffffffu, s0, 2);
            s1 += __shfl_xor_sync(0xffffffffu, s1, 1);
            s1 += __shfl_xor_sync(0xffffffffu, s1, 2);
            l0 = l0 * al0 + s0;
            l1 = l1 * al1 + s1;
        }
        if (++cur == 3) cur = 0;
    }

    // ---- epilogue: normalize, store single fp16 ----
    const float i0 = 1.f / l0, i1 = 1.f / l1;
    const size_t o0 = (((size_t)b * S_ + (size_t)qr0) * H_ + h) * D_;
    const size_t o1 = o0 + (size_t)8 * (H_ * D_);
#pragma unroll
    for (int nt = 0; nt < 16; nt++) {
        const int col = nt * 8 + tg * 2;
        *(uint32_t*)&Oa[o0 + col] = pkh(o[nt][0] * i0, o[nt][1] * i0);
        *(uint32_t*)&Oa[o1 + col] = pkh(o[nt][2] * i1, o[nt][3] * i1);
    }
}

// ---------------------------------------------------------------------------
extern "C" void kernel_launch(void* const* d_in, const int* in_sizes, int n_in,
                              void* d_out, int out_size)
{
    const float* x   = (const float*)d_in[0];
    const float* pe  = (const float*)d_in[1];
    const float* q_w = (const float*)d_in[2];
    const float* k_w = (const float*)d_in[3];
    const float* v_w = (const float*)d_in[4];
    const float* o_w = (const float*)d_in[5];
    const float* qnw = (const float*)d_in[6];
    const float* knw = (const float*)d_in[7];
    float* out = (float*)d_out;

    float *q, *k, *v;
    __half *x16, *qwh, *qwl, *kwh, *kwl, *vwh, *vwl, *owh, *owl;
    __half *q16, *kh, *kl, *vh, *vl, *at16;
    cudaGetSymbolAddress((void**)&q,    g_q);
    cudaGetSymbolAddress((void**)&k,    g_k);
    cudaGetSymbolAddress((void**)&v,    g_v);
    cudaGetSymbolAddress((void**)&x16,  g_x16);
    cudaGetSymbolAddress((void**)&qwh,  g_qwh);
    cudaGetSymbolAddress((void**)&qwl,  g_qwl);
    cudaGetSymbolAddress((void**)&kwh,  g_kwh);
    cudaGetSymbolAddress((void**)&kwl,  g_kwl);
    cudaGetSymbolAddress((void**)&vwh,  g_vwh);
    cudaGetSymbolAddress((void**)&vwl,  g_vwl);
    cudaGetSymbolAddress((void**)&owh,  g_owh);
    cudaGetSymbolAddress((void**)&owl,  g_owl);
    cudaGetSymbolAddress((void**)&q16,  g_q16);
    cudaGetSymbolAddress((void**)&kh,   g_kh16);
    cudaGetSymbolAddress((void**)&kl,   g_kl16);
    cudaGetSymbolAddress((void**)&vh,   g_vh16);
    cudaGetSymbolAddress((void**)&vl,   g_vl16);
    cudaGetSymbolAddress((void**)&at16, g_at16);

    cudaFuncSetAttribute(gemm_fp16x2, cudaFuncAttributeMaxDynamicSharedMemorySize,
                         GEMM_SMEM);
    cudaFuncSetAttribute(gemm_qkv, cudaFuncAttributeMaxDynamicSharedMemorySize,
                         GEMM_SMEM);
    cudaFuncSetAttribute(flash_mma, cudaFuncAttributeMaxDynamicSharedMemorySize,
                         FLASH3_SMEM);

    // 1) fused converts: x -> fp16 single; weights -> fp16 hi/lo
    split5<<<NSPLIT_TOT / 512, 256>>>(
        (const float4*)x, (const float4*)q_w, (const float4*)k_w,
        (const float4*)v_w, (const float4*)o_w,
        x16, qwh, qwl, kwh, kwl, vwh, vwl, owh, owl);

    // 2) fused Q/K/V projections (fp16x2 mma.sync)
    gemm_qkv<<<dim3(32, 32), 256, GEMM_SMEM>>>(x16, qwh, qwl, kwh, kwl,
                                               vwh, vwl, q, k, v, HID_);

    // 3) fused prep: rms+rope(Q->single, K->hi/lo) + split(V->hi/lo)
    prep_fused<<<PREP_QB + PREP_KB + PREP_VB, 128>>>(
        q, k, v, pe, qnw, knw, q16, kh, kl, vh, vl);

    // 4) causal GQA flash attention (fp16x2, 2 CTAs/SM)
    flash_mma<<<dim3(S_ / 64, H_, B_), 128, FLASH3_SMEM>>>(
        q16, kh, kl, vh, vl, at16);

    // 5) output projection (fp16x2 mma.sync)
    gemm_fp16x2<<<dim3(16, 32), 256, GEMM_SMEM>>>(at16, owh, owl, out, HID_, HID_);
}

// round 14
// speedup vs baseline: 1.7240x; 1.1978x over previous
#include <cuda_runtime.h>
#include <cuda_fp16.h>
#include <math.h>
#include <stdint.h>

#define B_   2
#define S_   2048
#define HID_ 2048
#define H_   16
#define KV_  8
#define D_   128
#define MROWS (B_ * S_)   // 4096

// ---------------------------------------------------------------------------
// Scratch (__device__ globals; allocation-free rule)
// ---------------------------------------------------------------------------
__device__ float g_q[(size_t)MROWS * H_ * D_];
__device__ float g_k[(size_t)MROWS * KV_ * D_];
__device__ float g_v[(size_t)MROWS * KV_ * D_];
__device__ __half g_x16[(size_t)MROWS * HID_];
__device__ __half g_qwh[(size_t)H_ * D_ * HID_];
__device__ __half g_qwl[(size_t)H_ * D_ * HID_];
__device__ __half g_kwh[(size_t)KV_ * D_ * HID_];
__device__ __half g_kwl[(size_t)KV_ * D_ * HID_];
__device__ __half g_vwh[(size_t)KV_ * D_ * HID_];
__device__ __half g_vwl[(size_t)KV_ * D_ * HID_];
__device__ __half g_owh[(size_t)HID_ * H_ * D_];
__device__ __half g_owl[(size_t)HID_ * H_ * D_];
__device__ __half g_q16[(size_t)MROWS * H_ * D_];
__device__ __half g_kh16[(size_t)MROWS * KV_ * D_];
__device__ __half g_kl16[(size_t)MROWS * KV_ * D_];
__device__ __half g_v16[(size_t)MROWS * KV_ * D_];
__device__ __half g_at16[(size_t)MROWS * H_ * D_];

// ---------------------------------------------------------------------------
// Helpers
// ---------------------------------------------------------------------------
__device__ __forceinline__ uint32_t smem_u32(const void* p) {
    uint32_t a;
    asm("{ .reg .u64 t; cvta.to.shared.u64 t, %1; cvt.u32.u64 %0, t; }"
        : "=r"(a) : "l"(p));
    return a;
}

__device__ __forceinline__ void cpasync16(uint32_t dst, const void* src) {
    asm volatile("cp.async.cg.shared.global [%0], [%1], 16;" :: "r"(dst), "l"(src));
}

#define LDSM_X4(r0, r1, r2, r3, addr)                                         \
    asm volatile("ldmatrix.sync.aligned.m8n8.x4.shared.b16 {%0,%1,%2,%3}, [%4];" \
                 : "=r"(r0), "=r"(r1), "=r"(r2), "=r"(r3) : "r"(addr))

#define LDSM_X4_T(r0, r1, r2, r3, addr)                                       \
    asm volatile("ldmatrix.sync.aligned.m8n8.x4.trans.shared.b16 {%0,%1,%2,%3}, [%4];" \
                 : "=r"(r0), "=r"(r1), "=r"(r2), "=r"(r3) : "r"(addr))

__device__ __forceinline__ void ldsm_x4(uint32_t& r0, uint32_t& r1,
                                        uint32_t& r2, uint32_t& r3, uint32_t addr) {
    LDSM_X4(r0, r1, r2, r3, addr);
}

// fp16 mma, fp32 accum
__device__ __forceinline__ void mma_h(float* c, const uint32_t* a,
                                      uint32_t b0, uint32_t b1) {
    asm volatile("mma.sync.aligned.m16n8k16.row.col.f32.f16.f16.f32 "
                 "{%0,%1,%2,%3}, {%4,%5,%6,%7}, {%8,%9}, {%0,%1,%2,%3};"
                 : "+f"(c[0]), "+f"(c[1]), "+f"(c[2]), "+f"(c[3])
                 : "r"(a[0]), "r"(a[1]), "r"(a[2]), "r"(a[3]), "r"(b0), "r"(b1));
}

__device__ __forceinline__ uint32_t pkh(float a, float b) {
    __half2 h = __floats2half2_rn(a, b);
    return *(uint32_t*)&h;
}
__device__ __forceinline__ void pkhl(float a, float b, uint32_t& hi, uint32_t& lo) {
    __half ha = __float2half_rn(a), hb = __float2half_rn(b);
    __half la = __float2half_rn(a - __half2float(ha));
    __half lb = __float2half_rn(b - __half2float(hb));
    hi = ((uint32_t)*(uint16_t*)&hb << 16) | (uint32_t)*(uint16_t*)&ha;
    lo = ((uint32_t)*(uint16_t*)&lb << 16) | (uint32_t)*(uint16_t*)&la;
}

// ---------------------------------------------------------------------------
// Fused split kernel: x -> single fp16; weights -> fp16 hi/lo.
// ---------------------------------------------------------------------------
#define NX4  (MROWS * HID_ / 4)        // 2097152
#define NQW4 (H_ * D_ * HID_ / 4)      // 1048576
#define NKW4 (KV_ * D_ * HID_ / 4)     // 524288
#define NSPLIT_TOT (NX4 + 2 * NQW4 + 2 * NKW4)   // 5242880

__device__ __forceinline__ void cvt_single(float4 v, __half* o16, int i) {
    uint2 p = make_uint2(pkh(v.x, v.y), pkh(v.z, v.w));
    *(uint2*)(o16 + 4 * (size_t)i) = p;
}
__device__ __forceinline__ void split_hl(float4 v, __half* h, __half* l, int i) {
    uint32_t h0, l0, h1, l1;
    pkhl(v.x, v.y, h0, l0);
    pkhl(v.z, v.w, h1, l1);
    *(uint2*)(h + 4 * (size_t)i) = make_uint2(h0, h1);
    *(uint2*)(l + 4 * (size_t)i) = make_uint2(l0, l1);
}

__global__ __launch_bounds__(256) void split5(
    const float4* __restrict__ x,  const float4* __restrict__ qw,
    const float4* __restrict__ kw, const float4* __restrict__ vw,
    const float4* __restrict__ ow,
    __half* x16,
    __half* qwh, __half* qwl, __half* kwh, __half* kwl,
    __half* vwh, __half* vwl, __half* owh, __half* owl)
{
    auto proc = [&](int i) {
        if (i < NX4) { cvt_single(x[i], x16, i); return; }
        i -= NX4;
        if (i < NQW4) { split_hl(qw[i], qwh, qwl, i); return; }
        i -= NQW4;
        if (i < NKW4) { split_hl(kw[i], kwh, kwl, i); return; }
        i -= NKW4;
        if (i < NKW4) { split_hl(vw[i], vwh, vwl, i); return; }
        i -= NKW4;
        split_hl(ow[i], owh, owl, i);
    };
    int gid = blockIdx.x * 256 + threadIdx.x;
    proc(2 * gid);
    proc(2 * gid + 1);
}

// ---------------------------------------------------------------------------
// fp16x2 mma.sync GEMM: C[m,n] = sum_k A[m,k]*B[n,k], A single, B hi/lo.
// 256 threads / 8 warps (2x4), warp tile 64x32; 2 CTAs/SM.
// ---------------------------------------------------------------------------
#define GK_      32
#define RSTR_B   80u
#define TILE_B   (128u * RSTR_B)
#define STAGE_B2 (3u * TILE_B)        // 30720
#define GEMM_SMEM (2 * 30720)

__device__ __forceinline__ void g_fill2(
    uint32_t dst, const __half* A16, const __half* Bh, const __half* Bl,
    int m0, int n0, int K, int k0, int tid)
{
#pragma unroll
    for (int i = 0; i < 6; i++) {
        int idx = tid + i * 256;
        int t   = idx >> 9;          // 0:A 1:Bh 2:Bl
        int rem = idx & 511;
        int r   = rem >> 2;
        int seg = rem & 3;
        const __half* src;
        if      (t == 0) src = A16 + (size_t)(m0 + r) * K + k0 + seg * 8;
        else if (t == 1) src = Bh  + (size_t)(n0 + r) * K + k0 + seg * 8;
        else             src = Bl  + (size_t)(n0 + r) * K + k0 + seg * 8;
        uint32_t d = dst + (uint32_t)t * TILE_B + (uint32_t)r * RSTR_B + (uint32_t)seg * 16u;
        cpasync16(d, src);
    }
}

__device__ __forceinline__ void gemm_body(
    const __half* A16, const __half* Bh, const __half* Bl,
    float* C, int N, int K, int m0, int n0, char* smem)
{
    const uint32_t sb  = smem_u32(smem);
    const int tid  = threadIdx.x;
    const int wid  = tid >> 5, lane = tid & 31;
    const int wm   = (wid >> 2) << 6;   // 0 or 64
    const int wn   = (wid & 3)  << 5;   // 0,32,64,96

    const uint32_t aoff = (uint32_t)(wm + (lane & 15)) * RSTR_B + (uint32_t)((lane >> 4) * 16);
    const uint32_t boff = (uint32_t)(wn + ((lane >> 4) << 3) + (lane & 7)) * RSTR_B
                        + (uint32_t)(((lane >> 3) & 1) * 16);

    float acc[4][4][4];
#pragma unroll
    for (int mi = 0; mi < 4; mi++)
#pragma unroll
        for (int ni = 0; ni < 4; ni++)
#pragma unroll
            for (int r = 0; r < 4; r++) acc[mi][ni][r] = 0.f;

    g_fill2(sb, A16, Bh, Bl, m0, n0, K, 0, tid);
    asm volatile("cp.async.commit_group;");

    const int nit = K / GK_;
    for (int it = 0; it < nit; ++it) {
        const int cur = it & 1;
        if (it + 1 < nit) {
            g_fill2(sb + (uint32_t)(cur ^ 1) * STAGE_B2, A16, Bh, Bl,
                    m0, n0, K, (it + 1) * GK_, tid);
            asm volatile("cp.async.commit_group;");
            asm volatile("cp.async.wait_group 1;");
        } else {
            asm volatile("cp.async.wait_group 0;");
        }
        __syncthreads();

        const uint32_t stg = sb + (uint32_t)cur * STAGE_B2;
        const uint32_t sA  = stg;
        const uint32_t sBh = stg + TILE_B;
        const uint32_t sBl = stg + 2u * TILE_B;

#pragma unroll
        for (int kh = 0; kh < 2; kh++) {
            const uint32_t kb = (uint32_t)kh * 32u;
            uint32_t ah[4][4], bh[4][2], bl[4][2];
#pragma unroll
            for (int mi = 0; mi < 4; mi++)
                ldsm_x4(ah[mi][0], ah[mi][1], ah[mi][2], ah[mi][3],
                        sA + aoff + (uint32_t)(mi * 16) * RSTR_B + kb);
#pragma unroll
            for (int nt = 0; nt < 2; nt++) {
                uint32_t r0, r1, r2, r3;
                ldsm_x4(r0, r1, r2, r3, sBh + boff + (uint32_t)(nt * 16) * RSTR_B + kb);
                bh[nt * 2 + 0][0] = r0; bh[nt * 2 + 0][1] = r1;
                bh[nt * 2 + 1][0] = r2; bh[nt * 2 + 1][1] = r3;
                ldsm_x4(r0, r1, r2, r3, sBl + boff + (uint32_t)(nt * 16) * RSTR_B + kb);
                bl[nt * 2 + 0][0] = r0; bl[nt * 2 + 0][1] = r1;
                bl[nt * 2 + 1][0] = r2; bl[nt * 2 + 1][1] = r3;
            }
#pragma unroll
            for (int mi = 0; mi < 4; mi++)
#pragma unroll
                for (int ni = 0; ni < 4; ni++) {
                    mma_h(acc[mi][ni], ah[mi], bh[ni][0], bh[ni][1]);
                    mma_h(acc[mi][ni], ah[mi], bl[ni][0], bl[ni][1]);
                }
        }
        __syncthreads();
    }

#pragma unroll
    for (int mi = 0; mi < 4; mi++) {
        const int row = m0 + wm + mi * 16 + (lane >> 2);
#pragma unroll
        for (int ni = 0; ni < 4; ni++) {
            const int col = n0 + wn + ni * 8 + (lane & 3) * 2;
            *(float2*)&C[(size_t)row * N + col] =
                make_float2(acc[mi][ni][0], acc[mi][ni][1]);
            *(float2*)&C[(size_t)(row + 8) * N + col] =
                make_float2(acc[mi][ni][2], acc[mi][ni][3]);
        }
    }
}

__global__ __launch_bounds__(256, 2) void gemm_fp16x2(
    const __half* __restrict__ A16, const __half* __restrict__ Bh,
    const __half* __restrict__ Bl, float* __restrict__ C, int N, int K)
{
    extern __shared__ __align__(128) char smem[];
    gemm_body(A16, Bh, Bl, C, N, K, blockIdx.y << 7, blockIdx.x << 7, smem);
}

// Fused Q/K/V projection: one launch, per-block weight/output select.
__global__ __launch_bounds__(256, 2) void gemm_qkv(
    const __half* __restrict__ x16,
    const __half* __restrict__ qwh, const __half* __restrict__ qwl,
    const __half* __restrict__ kwh, const __half* __restrict__ kwl,
    const __half* __restrict__ vwh, const __half* __restrict__ vwl,
    float* __restrict__ q, float* __restrict__ k, float* __restrict__ v, int K)
{
    extern __shared__ __align__(128) char smem[];
    const int bxx = blockIdx.x;
    const __half *Bh, *Bl;
    float* C; int N, n0;
    if (bxx < 16)      { Bh = qwh; Bl = qwl; C = q; N = 2048; n0 = bxx << 7; }
    else if (bxx < 24) { Bh = kwh; Bl = kwl; C = k; N = 1024; n0 = (bxx - 16) << 7; }
    else               { Bh = vwh; Bl = vwl; C = v; N = 1024; n0 = (bxx - 24) << 7; }
    gemm_body(x16, Bh, Bl, C, N, K, blockIdx.y << 7, n0, smem);
}

// ---------------------------------------------------------------------------
// Fused prep: warp-per-row RMSNorm+RoPE. Q -> single fp16; K -> fp16 hi/lo;
// V -> single fp16 convert. 128 threads/block.
// ---------------------------------------------------------------------------
template <bool SPLIT>
__device__ __forceinline__ void rms_rope_warp(
    const float* __restrict__ X, const float* __restrict__ pe,
    const float* __restrict__ w, int nheads, int row, int lane,
    __half* __restrict__ Xh, __half* __restrict__ Xl)
{
    const int bs = row / nheads;
    float4 v = *(const float4*)(X + (size_t)row * 128 + lane * 4);
    float ss = v.x * v.x + v.y * v.y + v.z * v.z + v.w * v.w;
#pragma unroll
    for (int o = 16; o > 0; o >>= 1) ss += __shfl_xor_sync(0xffffffffu, ss, o);
    float r = rsqrtf(ss * (1.f / 128.f) + 1e-6f);
    float4 wv = *(const float4*)(w + lane * 4);
    float xn[4] = {v.x * r * wv.x, v.y * r * wv.y, v.z * r * wv.z, v.w * r * wv.w};

    const int dbase = (lane & 15) * 4;
    float4 cv = *(const float4*)(pe + (size_t)bs * 128 + dbase);
    float4 sv = *(const float4*)(pe + (size_t)bs * 128 + 64 + dbase);
    float c[4] = {cv.x, cv.y, cv.z, cv.w};
    float s[4] = {sv.x, sv.y, sv.z, sv.w};
    float other[4];
#pragma unroll
    for (int j = 0; j < 4; j++) other[j] = __shfl_xor_sync(0xffffffffu, xn[j], 16);
    const bool low = (lane < 16);
    float out[4];
#pragma unroll
    for (int j = 0; j < 4; j++)
        out[j] = low ? (xn[j] * c[j] - other[j] * s[j])
                     : (other[j] * s[j] + xn[j] * c[j]);

    if (SPLIT) {
        uint32_t h0, l0, h1, l1;
        pkhl(out[0], out[1], h0, l0);
        pkhl(out[2], out[3], h1, l1);
        *(uint2*)(Xh + (size_t)row * 128 + lane * 4) = make_uint2(h0, h1);
        *(uint2*)(Xl + (size_t)row * 128 + lane * 4) = make_uint2(l0, l1);
    } else {
        *(uint2*)(Xh + (size_t)row * 128 + lane * 4) =
            make_uint2(pkh(out[0], out[1]), pkh(out[2], out[3]));
    }
}

#define PREP_QB (MROWS * H_ / 4)              // 16384
#define PREP_KB (MROWS * KV_ / 4)             // 8192
#define PREP_VB (MROWS * KV_ * D_ / 4 / 256)  // 4096

__global__ __launch_bounds__(128) void prep_fused(
    const float* __restrict__ q, const float* __restrict__ k,
    const float* __restrict__ v, const float* __restrict__ pe,
    const float* __restrict__ qnw, const float* __restrict__ knw,
    __half* q16, __half* kh, __half* kl, __half* v16)
{
    const int bid = blockIdx.x;
    const int lane = threadIdx.x & 31, wrp = threadIdx.x >> 5;
    if (bid < PREP_QB) {
        rms_rope_warp<false>(q, pe, qnw, H_, bid * 4 + wrp, lane, q16, nullptr);
    } else if (bid < PREP_QB + PREP_KB) {
        rms_rope_warp<true>(k, pe, knw, KV_, (bid - PREP_QB) * 4 + wrp, lane, kh, kl);
    } else {
        int i = (bid - PREP_QB - PREP_KB) * 256 + threadIdx.x;
        const float4* v4 = (const float4*)v;
        float4 a = v4[i];
        float4 b = v4[i + 128];
        cvt_single(a, v16, i);
        cvt_single(b, v16, i + 128);
    }
}

// ---------------------------------------------------------------------------
// Flash attention, fp16 (Q/P/V single, K hi/lo), causal GQA.
// BR=64 (4 warps x 16 rows), BC=32, 3-stage KV ring, 2 CTAs/SM.
// ---------------------------------------------------------------------------
#define F2STR   272u
#define F2_KH   0u
#define F2_KL   8704u
#define F2_VH   17408u
#define F2_STG  26112u
#define FLASH3_SMEM (3 * 26112)   // 78336

__global__ __launch_bounds__(128, 2) void flash_mma(
    const __half* __restrict__ Q16,
    const __half* __restrict__ Kh, const __half* __restrict__ Kl,
    const __half* __restrict__ V16,
    __half* __restrict__ Oa)
{
    extern __shared__ __align__(16) char smem[];
    const uint32_t sb = smem_u32(smem);
    const int tid = threadIdx.x, lane = tid & 31, w = tid >> 5;
    const int bx = gridDim.x - 1 - blockIdx.x;   // heavy diagonals first
    const int h = blockIdx.y, b = blockIdx.z, kvh = h >> 1;
    const int g = lane >> 2, tg = lane & 3;
    const int ntiles = 2 * bx + 2;               // >= 2

    // ---- prologue: cp.async Q (64 rows x 128 half, single) into stage-2 ----
    {
        const size_t qbase = (((size_t)b * S_ + (size_t)bx * 64) * H_ + h) * D_;
        const uint32_t qdst = sb + 2u * F2_STG;
#pragma unroll
        for (int i = 0; i < 8; i++) {
            int idx = tid + i * 128;
            int r = idx >> 4, seg = idx & 15;
            size_t src = qbase + (size_t)r * (H_ * D_) + seg * 8;
            cpasync16(qdst + (uint32_t)r * F2STR + (uint32_t)seg * 16u, Q16 + src);
        }
    }
    asm volatile("cp.async.commit_group;");

    auto fillKV = [&](int stage, int kt) {
        const size_t kbase = (((size_t)b * S_ + (size_t)kt * 32) * KV_ + kvh) * D_;
        const uint32_t sdst = sb + (uint32_t)stage * F2_STG;
#pragma unroll
        for (int i = 0; i < 4; i++) {
            int idx = tid + i * 128;
            int r = idx >> 4, seg = idx & 15;
            size_t src = kbase + (size_t)r * (KV_ * D_) + seg * 8;
            uint32_t dst = sdst + (uint32_t)r * F2STR + (uint32_t)seg * 16u;
            cpasync16(dst + F2_KH, Kh + src);
            cpasync16(dst + F2_KL, Kl + src);
            cpasync16(dst + F2_VH, V16 + src);
        }
        asm volatile("cp.async.commit_group;");
    };

    fillKV(0, 0);
    fillKV(1, 1);

    asm volatile("cp.async.wait_group 2;");   // Q complete (own portions)
    __syncthreads();                          // all portions visible

    // ---- Q fragments -> registers (single fp16) ----
    uint32_t qf[8][4];
    {
        const uint32_t aQ = sb + 2u * F2_STG
                          + (uint32_t)(w * 16 + (lane & 15)) * F2STR
                          + (uint32_t)((lane >> 4) * 16);
#pragma unroll
        for (int kb = 0; kb < 8; kb++)
            ldsm_x4(qf[kb][0], qf[kb][1], qf[kb][2], qf[kb][3], aQ + kb * 32);
    }

    float o[16][4];
#pragma unroll
    for (int i = 0; i < 16; i++)
#pragma unroll
        for (int j = 0; j < 4; j++) o[i][j] = 0.f;
    float m0 = -1e30f, m1 = -1e30f, l0 = 0.f, l1 = 0.f;

    const int qr0 = bx * 64 + w * 16 + g;
    const float sca2 = 0.12751744f;   // log2(e)/sqrt(128)

    int cur = 0;
    for (int kt = 0; kt < ntiles; kt++) {
        if (kt + 1 < ntiles) {
            asm volatile("cp.async.wait_group 1;");
        } else {
            asm volatile("cp.async.wait_group 0;");
        }
        __syncthreads();
        if (kt + 2 < ntiles) {
            int fs = cur + 2; if (fs >= 3) fs -= 3;
            fillKV(fs, kt + 2);
        }

        if (kt * 32 <= bx * 64 + w * 16 + 15) {
            const uint32_t stg = sb + (uint32_t)cur * F2_STG;
            const uint32_t bK  = stg + (uint32_t)((((lane >> 4) << 3) + (lane & 7)) * F2STR)
                               + (uint32_t)(((lane >> 3) & 1) * 16);

            // ---- S = Q (Kh + Kl), 2 products ----
            float sc[4][4];
#pragma unroll
            for (int i = 0; i < 4; i++)
#pragma unroll
                for (int j = 0; j < 4; j++) sc[i][j] = 0.f;

#pragma unroll
            for (int kb = 0; kb < 8; kb++) {
#pragma unroll
                for (int nt = 0; nt < 2; nt++) {
                    uint32_t kh0, kh1, kh2, kh3, kl0, kl1, kl2, kl3;
                    ldsm_x4(kh0, kh1, kh2, kh3,
                            bK + F2_KH + (uint32_t)(nt * 16) * F2STR + kb * 32);
                    ldsm_x4(kl0, kl1, kl2, kl3,
                            bK + F2_KL + (uint32_t)(nt * 16) * F2STR + kb * 32);
                    mma_h(sc[2 * nt],     qf[kb], kh0, kh1);
                    mma_h(sc[2 * nt],     qf[kb], kl0, kl1);
                    mma_h(sc[2 * nt + 1], qf[kb], kh2, kh3);
                    mma_h(sc[2 * nt + 1], qf[kb], kl2, kl3);
                }
            }

            // ---- scale (log2 domain) + causal mask ----
            const bool maskt = (kt * 32 + 31 > bx * 64 + w * 16);
            const int row0 = qr0, row1 = qr0 + 8, cb = kt * 32;
#pragma unroll
            for (int nt = 0; nt < 4; nt++) {
                int c0 = cb + nt * 8 + tg * 2;
                float v0 = sc[nt][0] * sca2, v1 = sc[nt][1] * sca2;
                float v2 = sc[nt][2] * sca2, v3 = sc[nt][3] * sca2;
                if (maskt) {
                    if (c0     > row0) v0 = -1e30f;
                    if (c0 + 1 > row0) v1 = -1e30f;
                    if (c0     > row1) v2 = -1e30f;
                    if (c0 + 1 > row1) v3 = -1e30f;
                }
                sc[nt][0] = v0; sc[nt][1] = v1; sc[nt][2] = v2; sc[nt][3] = v3;
            }

            // ---- row max ----
            float mx0 = -1e30f, mx1 = -1e30f;
#pragma unroll
            for (int nt = 0; nt < 4; nt++) {
                mx0 = fmaxf(mx0, fmaxf(sc[nt][0], sc[nt][1]));
                mx1 = fmaxf(mx1, fmaxf(sc[nt][2], sc[nt][3]));
            }
            mx0 = fmaxf(mx0, __shfl_xor_sync(0xffffffffu, mx0, 1));
            mx0 = fmaxf(mx0, __shfl_xor_sync(0xffffffffu, mx0, 2));
            mx1 = fmaxf(mx1, __shfl_xor_sync(0xffffffffu, mx1, 1));
            mx1 = fmaxf(mx1, __shfl_xor_sync(0xffffffffu, mx1, 2));
            const float mn0 = fmaxf(m0, mx0), mn1 = fmaxf(m1, mx1);
            const float al0 = exp2f(m0 - mn0), al1 = exp2f(m1 - mn1);
            m0 = mn0; m1 = mn1;
#pragma unroll
            for (int nt = 0; nt < 16; nt++) {
                o[nt][0] *= al0; o[nt][1] *= al0;
                o[nt][2] *= al1; o[nt][3] *= al1;
            }

            // ---- per-slice (2 x k16): exp2 -> pack (single) -> PV (V single) ----
            float s0 = 0.f, s1 = 0.f;
#pragma unroll
            for (int j = 0; j < 2; j++) {
                float p00 = exp2f(sc[2 * j][0] - mn0);
                float p01 = exp2f(sc[2 * j][1] - mn0);
                float p02 = exp2f(sc[2 * j][2] - mn1);
                float p03 = exp2f(sc[2 * j][3] - mn1);
                float p10 = exp2f(sc[2 * j + 1][0] - mn0);
                float p11 = exp2f(sc[2 * j + 1][1] - mn0);
                float p12 = exp2f(sc[2 * j + 1][2] - mn1);
                float p13 = exp2f(sc[2 * j + 1][3] - mn1);
                s0 += (p00 + p01) + (p10 + p11);
                s1 += (p02 + p03) + (p12 + p13);

                uint32_t ph[4];
                ph[0] = pkh(p00, p01);
                ph[1] = pkh(p02, p03);
                ph[2] = pkh(p10, p11);
                ph[3] = pkh(p12, p13);

                const uint32_t vrow = stg + F2_VH
                    + (uint32_t)((j * 16 + ((lane >> 3) & 1) * 8 + (lane & 7)) * F2STR)
                    + (uint32_t)((lane >> 4) * 16);
#pragma unroll
                for (int ntp = 0; ntp < 8; ntp++) {
                    uint32_t vh0, vh1, vh2, vh3;
                    LDSM_X4_T(vh0, vh1, vh2, vh3, vrow + ntp * 32);
                    mma_h(o[2 * ntp],     ph, vh0, vh1);
                    mma_h(o[2 * ntp + 1], ph, vh2, vh3);
                }
            }
            s0 += __shfl_xor_sync(0xffffffffu, s0, 1);
            s0 += __shfl_xor_sync(0xffffffffu, s0, 2);
            s1 += __shfl_xor_sync(0xffffffffu, s1, 1);
            s1 += __shfl_xor_sync(0xffffffffu, s1, 2);
            l0 = l0 * al0 + s0;
            l1 = l1 * al1 + s1;
        }
        if (++cur == 3) cur = 0;
    }

    // ---- epilogue: normalize, store single fp16 ----
    const float i0 = 1.f / l0, i1 = 1.f / l1;
    const size_t o0 = (((size_t)b * S_ + (size_t)qr0) * H_ + h) * D_;
    const size_t o1 = o0 + (size_t)8 * (H_ * D_);
#pragma unroll
    for (int nt = 0; nt < 16; nt++) {
        const int col = nt * 8 + tg * 2;
        *(uint32_t*)&Oa[o0 + col] = pkh(o[nt][0] * i0, o[nt][1] * i0);
        *(uint32_t*)&Oa[o1 + col] = pkh(o[nt][2] * i1, o[nt][3] * i1);
    }
}

// ---------------------------------------------------------------------------
extern "C" void kernel_launch(void* const* d_in, const int* in_sizes, int n_in,
                              void* d_out, int out_size)
{
    const float* x   = (const float*)d_in[0];
    const float* pe  = (const float*)d_in[1];
    const float* q_w = (const float*)d_in[2];
    const float* k_w = (const float*)d_in[3];
    const float* v_w = (const float*)d_in[4];
    const float* o_w = (const float*)d_in[5];
    const float* qnw = (const float*)d_in[6];
    const float* knw = (const float*)d_in[7];
    float* out = (float*)d_out;

    float *q, *k, *v;
    __half *x16, *qwh, *qwl, *kwh, *kwl, *vwh, *vwl, *owh, *owl;
    __half *q16, *kh, *kl, *v16, *at16;
    cudaGetSymbolAddress((void**)&q,    g_q);
    cudaGetSymbolAddress((void**)&k,    g_k);
    cudaGetSymbolAddress((void**)&v,    g_v);
    cudaGetSymbolAddress((void**)&x16,  g_x16);
    cudaGetSymbolAddress((void**)&qwh,  g_qwh);
    cudaGetSymbolAddress((void**)&qwl,  g_qwl);
    cudaGetSymbolAddress((void**)&kwh,  g_kwh);
    cudaGetSymbolAddress((void**)&kwl,  g_kwl);
    cudaGetSymbolAddress((void**)&vwh,  g_vwh);
    cudaGetSymbolAddress((void**)&vwl,  g_vwl);
    cudaGetSymbolAddress((void**)&owh,  g_owh);
    cudaGetSymbolAddress((void**)&owl,  g_owl);
    cudaGetSymbolAddress((void**)&q16,  g_q16);
    cudaGetSymbolAddress((void**)&kh,   g_kh16);
    cudaGetSymbolAddress((void**)&kl,   g_kl16);
    cudaGetSymbolAddress((void**)&v16,  g_v16);
    cudaGetSymbolAddress((void**)&at16, g_at16);

    cudaFuncSetAttribute(gemm_fp16x2, cudaFuncAttributeMaxDynamicSharedMemorySize,
                         GEMM_SMEM);
    cudaFuncSetAttribute(gemm_qkv, cudaFuncAttributeMaxDynamicSharedMemorySize,
                         GEMM_SMEM);
    cudaFuncSetAttribute(flash_mma, cudaFuncAttributeMaxDynamicSharedMemorySize,
                         FLASH3_SMEM);

    // 1) fused converts: x -> fp16 single; weights -> fp16 hi/lo
    split5<<<NSPLIT_TOT / 512, 256>>>(
        (const float4*)x, (const float4*)q_w, (const float4*)k_w,
        (const float4*)v_w, (const float4*)o_w,
        x16, qwh, qwl, kwh, kwl, vwh, vwl, owh, owl);

    // 2) fused Q/K/V projections (fp16x2 mma.sync, 2 CTAs/SM)
    gemm_qkv<<<dim3(32, 32), 256, GEMM_SMEM>>>(x16, qwh, qwl, kwh, kwl,
                                               vwh, vwl, q, k, v, HID_);

    // 3) fused prep: rms+rope(Q->single, K->hi/lo) + convert(V->single)
    prep_fused<<<PREP_QB + PREP_KB + PREP_VB, 128>>>(
        q, k, v, pe, qnw, knw, q16, kh, kl, v16);

    // 4) causal GQA flash attention (fp16, V single; 2 CTAs/SM)
    flash_mma<<<dim3(S_ / 64, H_, B_), 128, FLASH3_SMEM>>>(
        q16, kh, kl, v16, at16);

    // 5) output projection (fp16x2 mma.sync, 2 CTAs/SM)
    gemm_fp16x2<<<dim3(16, 32), 256, GEMM_SMEM>>>(at16, owh, owl, out, HID_, HID_);
}

// round 15
// speedup vs baseline: 2.4900x; 1.4443x over previous
#include <cuda_runtime.h>
#include <cuda_fp16.h>
#include <math.h>
#include <stdint.h>

#define B_   2
#define S_   2048
#define HID_ 2048
#define H_   16
#define KV_  8
#define D_   128
#define MROWS (B_ * S_)   // 4096

// ---------------------------------------------------------------------------
// Scratch (__device__ globals; allocation-free rule)
// ---------------------------------------------------------------------------
__device__ float g_q[(size_t)MROWS * H_ * D_];
__device__ float g_k[(size_t)MROWS * KV_ * D_];
__device__ float g_v[(size_t)MROWS * KV_ * D_];
__device__ __half g_x16[(size_t)MROWS * HID_];
__device__ __half g_qw16[(size_t)H_ * D_ * HID_];
__device__ __half g_kw16[(size_t)KV_ * D_ * HID_];
__device__ __half g_vw16[(size_t)KV_ * D_ * HID_];
__device__ __half g_ow16[(size_t)HID_ * H_ * D_];
__device__ __half g_q16[(size_t)MROWS * H_ * D_];
__device__ __half g_kh16[(size_t)MROWS * KV_ * D_];
__device__ __half g_kl16[(size_t)MROWS * KV_ * D_];
__device__ __half g_v16[(size_t)MROWS * KV_ * D_];
__device__ __half g_at16[(size_t)MROWS * H_ * D_];

// ---------------------------------------------------------------------------
// Helpers
// ---------------------------------------------------------------------------
__device__ __forceinline__ uint32_t smem_u32(const void* p) {
    uint32_t a;
    asm("{ .reg .u64 t; cvta.to.shared.u64 t, %1; cvt.u32.u64 %0, t; }"
        : "=r"(a) : "l"(p));
    return a;
}

__device__ __forceinline__ void cpasync16(uint32_t dst, const void* src) {
    asm volatile("cp.async.cg.shared.global [%0], [%1], 16;" :: "r"(dst), "l"(src));
}

#define LDSM_X4(r0, r1, r2, r3, addr)                                         \
    asm volatile("ldmatrix.sync.aligned.m8n8.x4.shared.b16 {%0,%1,%2,%3}, [%4];" \
                 : "=r"(r0), "=r"(r1), "=r"(r2), "=r"(r3) : "r"(addr))

#define LDSM_X4_T(r0, r1, r2, r3, addr)                                       \
    asm volatile("ldmatrix.sync.aligned.m8n8.x4.trans.shared.b16 {%0,%1,%2,%3}, [%4];" \
                 : "=r"(r0), "=r"(r1), "=r"(r2), "=r"(r3) : "r"(addr))

__device__ __forceinline__ void ldsm_x4(uint32_t& r0, uint32_t& r1,
                                        uint32_t& r2, uint32_t& r3, uint32_t addr) {
    LDSM_X4(r0, r1, r2, r3, addr);
}

// fp16 mma, fp32 accum
__device__ __forceinline__ void mma_h(float* c, const uint32_t* a,
                                      uint32_t b0, uint32_t b1) {
    asm volatile("mma.sync.aligned.m16n8k16.row.col.f32.f16.f16.f32 "
                 "{%0,%1,%2,%3}, {%4,%5,%6,%7}, {%8,%9}, {%0,%1,%2,%3};"
                 : "+f"(c[0]), "+f"(c[1]), "+f"(c[2]), "+f"(c[3])
                 : "r"(a[0]), "r"(a[1]), "r"(a[2]), "r"(a[3]), "r"(b0), "r"(b1));
}

__device__ __forceinline__ uint32_t pkh(float a, float b) {
    __half2 h = __floats2half2_rn(a, b);
    return *(uint32_t*)&h;
}
__device__ __forceinline__ void pkhl(float a, float b, uint32_t& hi, uint32_t& lo) {
    __half ha = __float2half_rn(a), hb = __float2half_rn(b);
    __half la = __float2half_rn(a - __half2float(ha));
    __half lb = __float2half_rn(b - __half2float(hb));
    hi = ((uint32_t)*(uint16_t*)&hb << 16) | (uint32_t)*(uint16_t*)&ha;
    lo = ((uint32_t)*(uint16_t*)&lb << 16) | (uint32_t)*(uint16_t*)&la;
}

// ---------------------------------------------------------------------------
// Fused convert kernel: all five arrays -> single fp16.
// ---------------------------------------------------------------------------
#define NX4  (MROWS * HID_ / 4)        // 2097152
#define NQW4 (H_ * D_ * HID_ / 4)      // 1048576
#define NKW4 (KV_ * D_ * HID_ / 4)     // 524288
#define NSPLIT_TOT (NX4 + 2 * NQW4 + 2 * NKW4)   // 5242880

__device__ __forceinline__ void cvt_single(float4 v, __half* o16, int i) {
    uint2 p = make_uint2(pkh(v.x, v.y), pkh(v.z, v.w));
    *(uint2*)(o16 + 4 * (size_t)i) = p;
}

__global__ __launch_bounds__(256) void split5(
    const float4* __restrict__ x,  const float4* __restrict__ qw,
    const float4* __restrict__ kw, const float4* __restrict__ vw,
    const float4* __restrict__ ow,
    __half* x16, __half* qw16, __half* kw16, __half* vw16, __half* ow16)
{
    auto proc = [&](int i) {
        if (i < NX4) { cvt_single(x[i], x16, i); return; }
        i -= NX4;
        if (i < NQW4) { cvt_single(qw[i], qw16, i); return; }
        i -= NQW4;
        if (i < NKW4) { cvt_single(kw[i], kw16, i); return; }
        i -= NKW4;
        if (i < NKW4) { cvt_single(vw[i], vw16, i); return; }
        i -= NKW4;
        cvt_single(ow[i], ow16, i);
    };
    int gid = blockIdx.x * 256 + threadIdx.x;
    proc(2 * gid);
    proc(2 * gid + 1);
}

// ---------------------------------------------------------------------------
// fp16 mma.sync GEMM: C[m,n] = sum_k A[m,k]*B[n,k], both single fp16.
// 256 threads / 8 warps (2x4), warp tile 64x32; 2 CTAs/SM.
// stage = A tile + B tile, each 128 rows x 32 half, stride 80B.
// ---------------------------------------------------------------------------
#define GK_      32
#define RSTR_B   80u
#define TILE_B   (128u * RSTR_B)
#define STAGE_B1 (2u * TILE_B)        // 20480
#define GEMM_SMEM (2 * 20480)

__device__ __forceinline__ void g_fill1(
    uint32_t dst, const __half* A16, const __half* B16,
    int m0, int n0, int K, int k0, int tid)
{
#pragma unroll
    for (int i = 0; i < 4; i++) {
        int idx = tid + i * 256;
        int t   = idx >> 9;          // 0:A 1:B
        int rem = idx & 511;
        int r   = rem >> 2;
        int seg = rem & 3;
        const __half* src = (t == 0) ? A16 + (size_t)(m0 + r) * K + k0 + seg * 8
                                     : B16 + (size_t)(n0 + r) * K + k0 + seg * 8;
        uint32_t d = dst + (uint32_t)t * TILE_B + (uint32_t)r * RSTR_B + (uint32_t)seg * 16u;
        cpasync16(d, src);
    }
}

__device__ __forceinline__ void gemm_body(
    const __half* A16, const __half* B16,
    float* C, int N, int K, int m0, int n0, char* smem)
{
    const uint32_t sb  = smem_u32(smem);
    const int tid  = threadIdx.x;
    const int wid  = tid >> 5, lane = tid & 31;
    const int wm   = (wid >> 2) << 6;   // 0 or 64
    const int wn   = (wid & 3)  << 5;   // 0,32,64,96

    const uint32_t aoff = (uint32_t)(wm + (lane & 15)) * RSTR_B + (uint32_t)((lane >> 4) * 16);
    const uint32_t boff = (uint32_t)(wn + ((lane >> 4) << 3) + (lane & 7)) * RSTR_B
                        + (uint32_t)(((lane >> 3) & 1) * 16);

    float acc[4][4][4];
#pragma unroll
    for (int mi = 0; mi < 4; mi++)
#pragma unroll
        for (int ni = 0; ni < 4; ni++)
#pragma unroll
            for (int r = 0; r < 4; r++) acc[mi][ni][r] = 0.f;

    g_fill1(sb, A16, B16, m0, n0, K, 0, tid);
    asm volatile("cp.async.commit_group;");

    const int nit = K / GK_;
    for (int it = 0; it < nit; ++it) {
        const int cur = it & 1;
        if (it + 1 < nit) {
            g_fill1(sb + (uint32_t)(cur ^ 1) * STAGE_B1, A16, B16,
                    m0, n0, K, (it + 1) * GK_, tid);
            asm volatile("cp.async.commit_group;");
            asm volatile("cp.async.wait_group 1;");
        } else {
            asm volatile("cp.async.wait_group 0;");
        }
        __syncthreads();

        const uint32_t stg = sb + (uint32_t)cur * STAGE_B1;
        const uint32_t sA  = stg;
        const uint32_t sB  = stg + TILE_B;

#pragma unroll
        for (int kh = 0; kh < 2; kh++) {
            const uint32_t kb = (uint32_t)kh * 32u;
            uint32_t ah[4][4], bh[4][2];
#pragma unroll
            for (int mi = 0; mi < 4; mi++)
                ldsm_x4(ah[mi][0], ah[mi][1], ah[mi][2], ah[mi][3],
                        sA + aoff + (uint32_t)(mi * 16) * RSTR_B + kb);
#pragma unroll
            for (int nt = 0; nt < 2; nt++) {
                uint32_t r0, r1, r2, r3;
                ldsm_x4(r0, r1, r2, r3, sB + boff + (uint32_t)(nt * 16) * RSTR_B + kb);
                bh[nt * 2 + 0][0] = r0; bh[nt * 2 + 0][1] = r1;
                bh[nt * 2 + 1][0] = r2; bh[nt * 2 + 1][1] = r3;
            }
#pragma unroll
            for (int mi = 0; mi < 4; mi++)
#pragma unroll
                for (int ni = 0; ni < 4; ni++)
                    mma_h(acc[mi][ni], ah[mi], bh[ni][0], bh[ni][1]);
        }
        __syncthreads();
    }

#pragma unroll
    for (int mi = 0; mi < 4; mi++) {
        const int row = m0 + wm + mi * 16 + (lane >> 2);
#pragma unroll
        for (int ni = 0; ni < 4; ni++) {
            const int col = n0 + wn + ni * 8 + (lane & 3) * 2;
            *(float2*)&C[(size_t)row * N + col] =
                make_float2(acc[mi][ni][0], acc[mi][ni][1]);
            *(float2*)&C[(size_t)(row + 8) * N + col] =
                make_float2(acc[mi][ni][2], acc[mi][ni][3]);
        }
    }
}

__global__ __launch_bounds__(256, 2) void gemm_fp16(
    const __half* __restrict__ A16, const __half* __restrict__ B16,
    float* __restrict__ C, int N, int K)
{
    extern __shared__ __align__(128) char smem[];
    gemm_body(A16, B16, C, N, K, blockIdx.y << 7, blockIdx.x << 7, smem);
}

// Fused Q/K/V projection: one launch, per-block weight/output select.
__global__ __launch_bounds__(256, 2) void gemm_qkv(
    const __half* __restrict__ x16,
    const __half* __restrict__ qw16, const __half* __restrict__ kw16,
    const __half* __restrict__ vw16,
    float* __restrict__ q, float* __restrict__ k, float* __restrict__ v, int K)
{
    extern __shared__ __align__(128) char smem[];
    const int bxx = blockIdx.x;
    const __half* B16;
    float* C; int N, n0;
    if (bxx < 16)      { B16 = qw16; C = q; N = 2048; n0 = bxx << 7; }
    else if (bxx < 24) { B16 = kw16; C = k; N = 1024; n0 = (bxx - 16) << 7; }
    else               { B16 = vw16; C = v; N = 1024; n0 = (bxx - 24) << 7; }
    gemm_body(x16, B16, C, N, K, blockIdx.y << 7, n0, smem);
}

// ---------------------------------------------------------------------------
// Fused prep: warp-per-row RMSNorm+RoPE. Q -> single fp16; K -> fp16 hi/lo;
// V -> single fp16 convert. 128 threads/block.
// ---------------------------------------------------------------------------
template <bool SPLIT>
__device__ __forceinline__ void rms_rope_warp(
    const float* __restrict__ X, const float* __restrict__ pe,
    const float* __restrict__ w, int nheads, int row, int lane,
    __half* __restrict__ Xh, __half* __restrict__ Xl)
{
    const int bs = row / nheads;
    float4 v = *(const float4*)(X + (size_t)row * 128 + lane * 4);
    float ss = v.x * v.x + v.y * v.y + v.z * v.z + v.w * v.w;
#pragma unroll
    for (int o = 16; o > 0; o >>= 1) ss += __shfl_xor_sync(0xffffffffu, ss, o);
    float r = rsqrtf(ss * (1.f / 128.f) + 1e-6f);
    float4 wv = *(const float4*)(w + lane * 4);
    float xn[4] = {v.x * r * wv.x, v.y * r * wv.y, v.z * r * wv.z, v.w * r * wv.w};

    const int dbase = (lane & 15) * 4;
    float4 cv = *(const float4*)(pe + (size_t)bs * 128 + dbase);
    float4 sv = *(const float4*)(pe + (size_t)bs * 128 + 64 + dbase);
    float c[4] = {cv.x, cv.y, cv.z, cv.w};
    float s[4] = {sv.x, sv.y, sv.z, sv.w};
    float other[4];
#pragma unroll
    for (int j = 0; j < 4; j++) other[j] = __shfl_xor_sync(0xffffffffu, xn[j], 16);
    const bool low = (lane < 16);
    float out[4];
#pragma unroll
    for (int j = 0; j < 4; j++)
        out[j] = low ? (xn[j] * c[j] - other[j] * s[j])
                     : (other[j] * s[j] + xn[j] * c[j]);

    if (SPLIT) {
        uint32_t h0, l0, h1, l1;
        pkhl(out[0], out[1], h0, l0);
        pkhl(out[2], out[3], h1, l1);
        *(uint2*)(Xh + (size_t)row * 128 + lane * 4) = make_uint2(h0, h1);
        *(uint2*)(Xl + (size_t)row * 128 + lane * 4) = make_uint2(l0, l1);
    } else {
        *(uint2*)(Xh + (size_t)row * 128 + lane * 4) =
            make_uint2(pkh(out[0], out[1]), pkh(out[2], out[3]));
    }
}

#define PREP_QB (MROWS * H_ / 4)              // 16384
#define PREP_KB (MROWS * KV_ / 4)             // 8192
#define PREP_VB (MROWS * KV_ * D_ / 4 / 256)  // 4096

__global__ __launch_bounds__(128) void prep_fused(
    const float* __restrict__ q, const float* __restrict__ k,
    const float* __restrict__ v, const float* __restrict__ pe,
    const float* __restrict__ qnw, const float* __restrict__ knw,
    __half* q16, __half* kh, __half* kl, __half* v16)
{
    const int bid = blockIdx.x;
    const int lane = threadIdx.x & 31, wrp = threadIdx.x >> 5;
    if (bid < PREP_QB) {
        rms_rope_warp<false>(q, pe, qnw, H_, bid * 4 + wrp, lane, q16, nullptr);
    } else if (bid < PREP_QB + PREP_KB) {
        rms_rope_warp<true>(k, pe, knw, KV_, (bid - PREP_QB) * 4 + wrp, lane, kh, kl);
    } else {
        int i = (bid - PREP_QB - PREP_KB) * 256 + threadIdx.x;
        const float4* v4 = (const float4*)v;
        float4 a = v4[i];
        float4 b = v4[i + 128];
        cvt_single(a, v16, i);
        cvt_single(b, v16, i + 128);
    }
}

// ---------------------------------------------------------------------------
// Flash attention, fp16 (Q/P/V single, K hi/lo), causal GQA.
// BR=64 (4 warps x 16 rows), BC=32, 3-stage KV ring, 2 CTAs/SM. (unchanged)
// ---------------------------------------------------------------------------
#define F2STR   272u
#define F2_KH   0u
#define F2_KL   8704u
#define F2_VH   17408u
#define F2_STG  26112u
#define FLASH3_SMEM (3 * 26112)   // 78336

__global__ __launch_bounds__(128, 2) void flash_mma(
    const __half* __restrict__ Q16,
    const __half* __restrict__ Kh, const __half* __restrict__ Kl,
    const __half* __restrict__ V16,
    __half* __restrict__ Oa)
{
    extern __shared__ __align__(16) char smem[];
    const uint32_t sb = smem_u32(smem);
    const int tid = threadIdx.x, lane = tid & 31, w = tid >> 5;
    const int bx = gridDim.x - 1 - blockIdx.x;   // heavy diagonals first
    const int h = blockIdx.y, b = blockIdx.z, kvh = h >> 1;
    const int g = lane >> 2, tg = lane & 3;
    const int ntiles = 2 * bx + 2;               // >= 2

    // ---- prologue: cp.async Q (64 rows x 128 half, single) into stage-2 ----
    {
        const size_t qbase = (((size_t)b * S_ + (size_t)bx * 64) * H_ + h) * D_;
        const uint32_t qdst = sb + 2u * F2_STG;
#pragma unroll
        for (int i = 0; i < 8; i++) {
            int idx = tid + i * 128;
            int r = idx >> 4, seg = idx & 15;
            size_t src = qbase + (size_t)r * (H_ * D_) + seg * 8;
            cpasync16(qdst + (uint32_t)r * F2STR + (uint32_t)seg * 16u, Q16 + src);
        }
    }
    asm volatile("cp.async.commit_group;");

    auto fillKV = [&](int stage, int kt) {
        const size_t kbase = (((size_t)b * S_ + (size_t)kt * 32) * KV_ + kvh) * D_;
        const uint32_t sdst = sb + (uint32_t)stage * F2_STG;
#pragma unroll
        for (int i = 0; i < 4; i++) {
            int idx = tid + i * 128;
            int r = idx >> 4, seg = idx & 15;
            size_t src = kbase + (size_t)r * (KV_ * D_) + seg * 8;
            uint32_t dst = sdst + (uint32_t)r * F2STR + (uint32_t)seg * 16u;
            cpasync16(dst + F2_KH, Kh + src);
            cpasync16(dst + F2_KL, Kl + src);
            cpasync16(dst + F2_VH, V16 + src);
        }
        asm volatile("cp.async.commit_group;");
    };

    fillKV(0, 0);
    fillKV(1, 1);

    asm volatile("cp.async.wait_group 2;");   // Q complete (own portions)
    __syncthreads();                          // all portions visible

    // ---- Q fragments -> registers (single fp16) ----
    uint32_t qf[8][4];
    {
        const uint32_t aQ = sb + 2u * F2_STG
                          + (uint32_t)(w * 16 + (lane & 15)) * F2STR
                          + (uint32_t)((lane >> 4) * 16);
#pragma unroll
        for (int kb = 0; kb < 8; kb++)
            ldsm_x4(qf[kb][0], qf[kb][1], qf[kb][2], qf[kb][3], aQ + kb * 32);
    }

    float o[16][4];
#pragma unroll
    for (int i = 0; i < 16; i++)
#pragma unroll
        for (int j = 0; j < 4; j++) o[i][j] = 0.f;
    float m0 = -1e30f, m1 = -1e30f, l0 = 0.f, l1 = 0.f;

    const int qr0 = bx * 64 + w * 16 + g;
    const float sca2 = 0.12751744f;   // log2(e)/sqrt(128)

    int cur = 0;
    for (int kt = 0; kt < ntiles; kt++) {
        if (kt + 1 < ntiles) {
            asm volatile("cp.async.wait_group 1;");
        } else {
            asm volatile("cp.async.wait_group 0;");
        }
        __syncthreads();
        if (kt + 2 < ntiles) {
            int fs = cur + 2; if (fs >= 3) fs -= 3;
            fillKV(fs, kt + 2);
        }

        if (kt * 32 <= bx * 64 + w * 16 + 15) {
            const uint32_t stg = sb + (uint32_t)cur * F2_STG;
            const uint32_t bK  = stg + (uint32_t)((((lane >> 4) << 3) + (lane & 7)) * F2STR)
                               + (uint32_t)(((lane >> 3) & 1) * 16);

            // ---- S = Q (Kh + Kl), 2 products ----
            float sc[4][4];
#pragma unroll
            for (int i = 0; i < 4; i++)
#pragma unroll
                for (int j = 0; j < 4; j++) sc[i][j] = 0.f;

#pragma unroll
            for (int kb = 0; kb < 8; kb++) {
#pragma unroll
                for (int nt = 0; nt < 2; nt++) {
                    uint32_t kh0, kh1, kh2, kh3, kl0, kl1, kl2, kl3;
                    ldsm_x4(kh0, kh1, kh2, kh3,
                            bK + F2_KH + (uint32_t)(nt * 16) * F2STR + kb * 32);
                    ldsm_x4(kl0, kl1, kl2, kl3,
                            bK + F2_KL + (uint32_t)(nt * 16) * F2STR + kb * 32);
                    mma_h(sc[2 * nt],     qf[kb], kh0, kh1);
                    mma_h(sc[2 * nt],     qf[kb], kl0, kl1);
                    mma_h(sc[2 * nt + 1], qf[kb], kh2, kh3);
                    mma_h(sc[2 * nt + 1], qf[kb], kl2, kl3);
                }
            }

            // ---- scale (log2 domain) + causal mask ----
            const bool maskt = (kt * 32 + 31 > bx * 64 + w * 16);
            const int row0 = qr0, row1 = qr0 + 8, cb = kt * 32;
#pragma unroll
            for (int nt = 0; nt < 4; nt++) {
                int c0 = cb + nt * 8 + tg * 2;
                float v0 = sc[nt][0] * sca2, v1 = sc[nt][1] * sca2;
                float v2 = sc[nt][2] * sca2, v3 = sc[nt][3] * sca2;
                if (maskt) {
                    if (c0     > row0) v0 = -1e30f;
                    if (c0 + 1 > row0) v1 = -1e30f;
                    if (c0     > row1) v2 = -1e30f;
                    if (c0 + 1 > row1) v3 = -1e30f;
                }
                sc[nt][0] = v0; sc[nt][1] = v1; sc[nt][2] = v2; sc[nt][3] = v3;
            }

            // ---- row max ----
            float mx0 = -1e30f, mx1 = -1e30f;
#pragma unroll
            for (int nt = 0; nt < 4; nt++) {
                mx0 = fmaxf(mx0, fmaxf(sc[nt][0], sc[nt][1]));
                mx1 = fmaxf(mx1, fmaxf(sc[nt][2], sc[nt][3]));
            }
            mx0 = fmaxf(mx0, __shfl_xor_sync(0xffffffffu, mx0, 1));
            mx0 = fmaxf(mx0, __shfl_xor_sync(0xffffffffu, mx0, 2));
            mx1 = fmaxf(mx1, __shfl_xor_sync(0xffffffffu, mx1, 1));
            mx1 = fmaxf(mx1, __shfl_xor_sync(0xffffffffu, mx1, 2));
            const float mn0 = fmaxf(m0, mx0), mn1 = fmaxf(m1, mx1);
            const float al0 = exp2f(m0 - mn0), al1 = exp2f(m1 - mn1);
            m0 = mn0; m1 = mn1;
#pragma unroll
            for (int nt = 0; nt < 16; nt++) {
                o[nt][0] *= al0; o[nt][1] *= al0;
                o[nt][2] *= al1; o[nt][3] *= al1;
            }

            // ---- per-slice (2 x k16): exp2 -> pack (single) -> PV (V single) ----
            float s0 = 0.f, s1 = 0.f;
#pragma unroll
            for (int j = 0; j < 2; j++) {
                float p00 = exp2f(sc[2 * j][0] - mn0);
                float p01 = exp2f(sc[2 * j][1] - mn0);
                float p02 = exp2f(sc[2 * j][2] - mn1);
                float p03 = exp2f(sc[2 * j][3] - mn1);
                float p10 = exp2f(sc[2 * j + 1][0] - mn0);
                float p11 = exp2f(sc[2 * j + 1][1] - mn0);
                float p12 = exp2f(sc[2 * j + 1][2] - mn1);
                float p13 = exp2f(sc[2 * j + 1][3] - mn1);
                s0 += (p00 + p01) + (p10 + p11);
                s1 += (p02 + p03) + (p12 + p13);

                uint32_t ph[4];
                ph[0] = pkh(p00, p01);
                ph[1] = pkh(p02, p03);
                ph[2] = pkh(p10, p11);
                ph[3] = pkh(p12, p13);

                const uint32_t vrow = stg + F2_VH
                    + (uint32_t)((j * 16 + ((lane >> 3) & 1) * 8 + (lane & 7)) * F2STR)
                    + (uint32_t)((lane >> 4) * 16);
#pragma unroll
                for (int ntp = 0; ntp < 8; ntp++) {
                    uint32_t vh0, vh1, vh2, vh3;
                    LDSM_X4_T(vh0, vh1, vh2, vh3, vrow + ntp * 32);
                    mma_h(o[2 * ntp],     ph, vh0, vh1);
                    mma_h(o[2 * ntp + 1], ph, vh2, vh3);
                }
            }
            s0 += __shfl_xor_sync(0xffffffffu, s0, 1);
            s0 += __shfl_xor_sync(0xffffffffu, s0, 2);
            s1 += __shfl_xor_sync(0xffffffffu, s1, 1);
            s1 += __shfl_xor_sync(0xffffffffu, s1, 2);
            l0 = l0 * al0 + s0;
            l1 = l1 * al1 + s1;
        }
        if (++cur == 3) cur = 0;
    }

    // ---- epilogue: normalize, store single fp16 ----
    const float i0 = 1.f / l0, i1 = 1.f / l1;
    const size_t o0 = (((size_t)b * S_ + (size_t)qr0) * H_ + h) * D_;
    const size_t o1 = o0 + (size_t)8 * (H_ * D_);
#pragma unroll
    for (int nt = 0; nt < 16; nt++) {
        const int col = nt * 8 + tg * 2;
        *(uint32_t*)&Oa[o0 + col] = pkh(o[nt][0] * i0, o[nt][1] * i0);
        *(uint32_t*)&Oa[o1 + col] = pkh(o[nt][2] * i1, o[nt][3] * i1);
    }
}

// ---------------------------------------------------------------------------
extern "C" void kernel_launch(void* const* d_in, const int* in_sizes, int n_in,
                              void* d_out, int out_size)
{
    const float* x   = (const float*)d_in[0];
    const float* pe  = (const float*)d_in[1];
    const float* q_w = (const float*)d_in[2];
    const float* k_w = (const float*)d_in[3];
    const float* v_w = (const float*)d_in[4];
    const float* o_w = (const float*)d_in[5];
    const float* qnw = (const float*)d_in[6];
    const float* knw = (const float*)d_in[7];
    float* out = (float*)d_out;

    float *q, *k, *v;
    __half *x16, *qw16, *kw16, *vw16, *ow16;
    __half *q16, *kh, *kl, *v16, *at16;
    cudaGetSymbolAddress((void**)&q,    g_q);
    cudaGetSymbolAddress((void**)&k,    g_k);
    cudaGetSymbolAddress((void**)&v,    g_v);
    cudaGetSymbolAddress((void**)&x16,  g_x16);
    cudaGetSymbolAddress((void**)&qw16, g_qw16);
    cudaGetSymbolAddress((void**)&kw16, g_kw16);
    cudaGetSymbolAddress((void**)&vw16, g_vw16);
    cudaGetSymbolAddress((void**)&ow16, g_ow16);
    cudaGetSymbolAddress((void**)&q16,  g_q16);
    cudaGetSymbolAddress((void**)&kh,   g_kh16);
    cudaGetSymbolAddress((void**)&kl,   g_kl16);
    cudaGetSymbolAddress((void**)&v16,  g_v16);
    cudaGetSymbolAddress((void**)&at16, g_at16);

    cudaFuncSetAttribute(gemm_fp16, cudaFuncAttributeMaxDynamicSharedMemorySize,
                         GEMM_SMEM);
    cudaFuncSetAttribute(gemm_qkv, cudaFuncAttributeMaxDynamicSharedMemorySize,
                         GEMM_SMEM);
    cudaFuncSetAttribute(flash_mma, cudaFuncAttributeMaxDynamicSharedMemorySize,
                         FLASH3_SMEM);

    // 1) fused converts: all inputs -> single fp16
    split5<<<NSPLIT_TOT / 512, 256>>>(
        (const float4*)x, (const float4*)q_w, (const float4*)k_w,
        (const float4*)v_w, (const float4*)o_w,
        x16, qw16, kw16, vw16, ow16);

    // 2) fused Q/K/V projections (fp16 mma.sync, 2 CTAs/SM)
    gemm_qkv<<<dim3(32, 32), 256, GEMM_SMEM>>>(x16, qw16, kw16, vw16,
                                               q, k, v, HID_);

    // 3) fused prep: rms+rope(Q->single, K->hi/lo) + convert(V->single)
    prep_fused<<<PREP_QB + PREP_KB + PREP_VB, 128>>>(
        q, k, v, pe, qnw, knw, q16, kh, kl, v16);

    // 4) causal GQA flash attention (fp16, V single, K hi/lo; 2 CTAs/SM)
    flash_mma<<<dim3(S_ / 64, H_, B_), 128, FLASH3_SMEM>>>(
        q16, kh, kl, v16, at16);

    // 5) output projection (fp16 mma.sync, 2 CTAs/SM)
    gemm_fp16<<<dim3(16, 32), 256, GEMM_SMEM>>>(at16, ow16, out, HID_, HID_);
}

// round 16
// speedup vs baseline: 2.8462x; 1.1431x over previous
#include <cuda_runtime.h>
#include <cuda_fp16.h>
#include <math.h>
#include <stdint.h>

#define B_   2
#define S_   2048
#define HID_ 2048
#define H_   16
#define KV_  8
#define D_   128
#define MROWS (B_ * S_)   // 4096

// ---------------------------------------------------------------------------
// Scratch (__device__ globals; allocation-free rule)
// ---------------------------------------------------------------------------
__device__ float g_q[(size_t)MROWS * H_ * D_];
__device__ float g_k[(size_t)MROWS * KV_ * D_];
__device__ float g_v[(size_t)MROWS * KV_ * D_];
__device__ __half g_x16[(size_t)MROWS * HID_];
__device__ __half g_qw16[(size_t)H_ * D_ * HID_];
__device__ __half g_kw16[(size_t)KV_ * D_ * HID_];
__device__ __half g_vw16[(size_t)KV_ * D_ * HID_];
__device__ __half g_ow16[(size_t)HID_ * H_ * D_];
__device__ __half g_q16[(size_t)MROWS * H_ * D_];
__device__ __half g_k16[(size_t)MROWS * KV_ * D_];
__device__ __half g_v16[(size_t)MROWS * KV_ * D_];
__device__ __half g_at16[(size_t)MROWS * H_ * D_];

// ---------------------------------------------------------------------------
// Helpers
// ---------------------------------------------------------------------------
__device__ __forceinline__ uint32_t smem_u32(const void* p) {
    uint32_t a;
    asm("{ .reg .u64 t; cvta.to.shared.u64 t, %1; cvt.u32.u64 %0, t; }"
        : "=r"(a) : "l"(p));
    return a;
}

__device__ __forceinline__ void cpasync16(uint32_t dst, const void* src) {
    asm volatile("cp.async.cg.shared.global [%0], [%1], 16;" :: "r"(dst), "l"(src));
}

#define LDSM_X4(r0, r1, r2, r3, addr)                                         \
    asm volatile("ldmatrix.sync.aligned.m8n8.x4.shared.b16 {%0,%1,%2,%3}, [%4];" \
                 : "=r"(r0), "=r"(r1), "=r"(r2), "=r"(r3) : "r"(addr))

#define LDSM_X4_T(r0, r1, r2, r3, addr)                                       \
    asm volatile("ldmatrix.sync.aligned.m8n8.x4.trans.shared.b16 {%0,%1,%2,%3}, [%4];" \
                 : "=r"(r0), "=r"(r1), "=r"(r2), "=r"(r3) : "r"(addr))

__device__ __forceinline__ void ldsm_x4(uint32_t& r0, uint32_t& r1,
                                        uint32_t& r2, uint32_t& r3, uint32_t addr) {
    LDSM_X4(r0, r1, r2, r3, addr);
}

// fp16 mma, fp32 accum
__device__ __forceinline__ void mma_h(float* c, const uint32_t* a,
                                      uint32_t b0, uint32_t b1) {
    asm volatile("mma.sync.aligned.m16n8k16.row.col.f32.f16.f16.f32 "
                 "{%0,%1,%2,%3}, {%4,%5,%6,%7}, {%8,%9}, {%0,%1,%2,%3};"
                 : "+f"(c[0]), "+f"(c[1]), "+f"(c[2]), "+f"(c[3])
                 : "r"(a[0]), "r"(a[1]), "r"(a[2]), "r"(a[3]), "r"(b0), "r"(b1));
}

__device__ __forceinline__ uint32_t pkh(float a, float b) {
    __half2 h = __floats2half2_rn(a, b);
    return *(uint32_t*)&h;
}

// ---------------------------------------------------------------------------
// Fused convert kernel: all five arrays -> single fp16.
// ---------------------------------------------------------------------------
#define NX4  (MROWS * HID_ / 4)        // 2097152
#define NQW4 (H_ * D_ * HID_ / 4)      // 1048576
#define NKW4 (KV_ * D_ * HID_ / 4)     // 524288
#define NSPLIT_TOT (NX4 + 2 * NQW4 + 2 * NKW4)   // 5242880

__device__ __forceinline__ void cvt_single(float4 v, __half* o16, int i) {
    uint2 p = make_uint2(pkh(v.x, v.y), pkh(v.z, v.w));
    *(uint2*)(o16 + 4 * (size_t)i) = p;
}

__global__ __launch_bounds__(256) void split5(
    const float4* __restrict__ x,  const float4* __restrict__ qw,
    const float4* __restrict__ kw, const float4* __restrict__ vw,
    const float4* __restrict__ ow,
    __half* x16, __half* qw16, __half* kw16, __half* vw16, __half* ow16)
{
    auto proc = [&](int i) {
        if (i < NX4) { cvt_single(x[i], x16, i); return; }
        i -= NX4;
        if (i < NQW4) { cvt_single(qw[i], qw16, i); return; }
        i -= NQW4;
        if (i < NKW4) { cvt_single(kw[i], kw16, i); return; }
        i -= NKW4;
        if (i < NKW4) { cvt_single(vw[i], vw16, i); return; }
        i -= NKW4;
        cvt_single(ow[i], ow16, i);
    };
    int gid = blockIdx.x * 256 + threadIdx.x;
    proc(2 * gid);
    proc(2 * gid + 1);
}

// ---------------------------------------------------------------------------
// fp16 mma.sync GEMM: C[m,n] = sum_k A[m,k]*B[n,k], both single fp16.
// 256 threads / 8 warps (2x4), warp tile 64x32; 2 CTAs/SM. (validated R15)
// ---------------------------------------------------------------------------
#define GK_      32
#define RSTR_B   80u
#define TILE_B   (128u * RSTR_B)
#define STAGE_B1 (2u * TILE_B)        // 20480
#define GEMM_SMEM (2 * 20480)

__device__ __forceinline__ void g_fill1(
    uint32_t dst, const __half* A16, const __half* B16,
    int m0, int n0, int K, int k0, int tid)
{
#pragma unroll
    for (int i = 0; i < 4; i++) {
        int idx = tid + i * 256;
        int t   = idx >> 9;          // 0:A 1:B
        int rem = idx & 511;
        int r   = rem >> 2;
        int seg = rem & 3;
        const __half* src = (t == 0) ? A16 + (size_t)(m0 + r) * K + k0 + seg * 8
                                     : B16 + (size_t)(n0 + r) * K + k0 + seg * 8;
        uint32_t d = dst + (uint32_t)t * TILE_B + (uint32_t)r * RSTR_B + (uint32_t)seg * 16u;
        cpasync16(d, src);
    }
}

__device__ __forceinline__ void gemm_body(
    const __half* A16, const __half* B16,
    float* C, int N, int K, int m0, int n0, char* smem)
{
    const uint32_t sb  = smem_u32(smem);
    const int tid  = threadIdx.x;
    const int wid  = tid >> 5, lane = tid & 31;
    const int wm   = (wid >> 2) << 6;   // 0 or 64
    const int wn   = (wid & 3)  << 5;   // 0,32,64,96

    const uint32_t aoff = (uint32_t)(wm + (lane & 15)) * RSTR_B + (uint32_t)((lane >> 4) * 16);
    const uint32_t boff = (uint32_t)(wn + ((lane >> 4) << 3) + (lane & 7)) * RSTR_B
                        + (uint32_t)(((lane >> 3) & 1) * 16);

    float acc[4][4][4];
#pragma unroll
    for (int mi = 0; mi < 4; mi++)
#pragma unroll
        for (int ni = 0; ni < 4; ni++)
#pragma unroll
            for (int r = 0; r < 4; r++) acc[mi][ni][r] = 0.f;

    g_fill1(sb, A16, B16, m0, n0, K, 0, tid);
    asm volatile("cp.async.commit_group;");

    const int nit = K / GK_;
    for (int it = 0; it < nit; ++it) {
        const int cur = it & 1;
        if (it + 1 < nit) {
            g_fill1(sb + (uint32_t)(cur ^ 1) * STAGE_B1, A16, B16,
                    m0, n0, K, (it + 1) * GK_, tid);
            asm volatile("cp.async.commit_group;");
            asm volatile("cp.async.wait_group 1;");
        } else {
            asm volatile("cp.async.wait_group 0;");
        }
        __syncthreads();

        const uint32_t stg = sb + (uint32_t)cur * STAGE_B1;
        const uint32_t sA  = stg;
        const uint32_t sB  = stg + TILE_B;

#pragma unroll
        for (int kh = 0; kh < 2; kh++) {
            const uint32_t kb = (uint32_t)kh * 32u;
            uint32_t ah[4][4], bh[4][2];
#pragma unroll
            for (int mi = 0; mi < 4; mi++)
                ldsm_x4(ah[mi][0], ah[mi][1], ah[mi][2], ah[mi][3],
                        sA + aoff + (uint32_t)(mi * 16) * RSTR_B + kb);
#pragma unroll
            for (int nt = 0; nt < 2; nt++) {
                uint32_t r0, r1, r2, r3;
                ldsm_x4(r0, r1, r2, r3, sB + boff + (uint32_t)(nt * 16) * RSTR_B + kb);
                bh[nt * 2 + 0][0] = r0; bh[nt * 2 + 0][1] = r1;
                bh[nt * 2 + 1][0] = r2; bh[nt * 2 + 1][1] = r3;
            }
#pragma unroll
            for (int mi = 0; mi < 4; mi++)
#pragma unroll
                for (int ni = 0; ni < 4; ni++)
                    mma_h(acc[mi][ni], ah[mi], bh[ni][0], bh[ni][1]);
        }
        __syncthreads();
    }

#pragma unroll
    for (int mi = 0; mi < 4; mi++) {
        const int row = m0 + wm + mi * 16 + (lane >> 2);
#pragma unroll
        for (int ni = 0; ni < 4; ni++) {
            const int col = n0 + wn + ni * 8 + (lane & 3) * 2;
            *(float2*)&C[(size_t)row * N + col] =
                make_float2(acc[mi][ni][0], acc[mi][ni][1]);
            *(float2*)&C[(size_t)(row + 8) * N + col] =
                make_float2(acc[mi][ni][2], acc[mi][ni][3]);
        }
    }
}

__global__ __launch_bounds__(256, 2) void gemm_fp16(
    const __half* __restrict__ A16, const __half* __restrict__ B16,
    float* __restrict__ C, int N, int K)
{
    extern __shared__ __align__(128) char smem[];
    gemm_body(A16, B16, C, N, K, blockIdx.y << 7, blockIdx.x << 7, smem);
}

// Fused Q/K/V projection: one launch, per-block weight/output select.
__global__ __launch_bounds__(256, 2) void gemm_qkv(
    const __half* __restrict__ x16,
    const __half* __restrict__ qw16, const __half* __restrict__ kw16,
    const __half* __restrict__ vw16,
    float* __restrict__ q, float* __restrict__ k, float* __restrict__ v, int K)
{
    extern __shared__ __align__(128) char smem[];
    const int bxx = blockIdx.x;
    const __half* B16;
    float* C; int N, n0;
    if (bxx < 16)      { B16 = qw16; C = q; N = 2048; n0 = bxx << 7; }
    else if (bxx < 24) { B16 = kw16; C = k; N = 1024; n0 = (bxx - 16) << 7; }
    else               { B16 = vw16; C = v; N = 1024; n0 = (bxx - 24) << 7; }
    gemm_body(x16, B16, C, N, K, blockIdx.y << 7, n0, smem);
}

// ---------------------------------------------------------------------------
// Fused prep: warp-per-row RMSNorm+RoPE (Q, K -> single fp16) + V convert.
// 128 threads/block.
// ---------------------------------------------------------------------------
__device__ __forceinline__ void rms_rope_warp(
    const float* __restrict__ X, const float* __restrict__ pe,
    const float* __restrict__ w, int nheads, int row, int lane,
    __half* __restrict__ X16)
{
    const int bs = row / nheads;
    float4 v = *(const float4*)(X + (size_t)row * 128 + lane * 4);
    float ss = v.x * v.x + v.y * v.y + v.z * v.z + v.w * v.w;
#pragma unroll
    for (int o = 16; o > 0; o >>= 1) ss += __shfl_xor_sync(0xffffffffu, ss, o);
    float r = rsqrtf(ss * (1.f / 128.f) + 1e-6f);
    float4 wv = *(const float4*)(w + lane * 4);
    float xn[4] = {v.x * r * wv.x, v.y * r * wv.y, v.z * r * wv.z, v.w * r * wv.w};

    const int dbase = (lane & 15) * 4;
    float4 cv = *(const float4*)(pe + (size_t)bs * 128 + dbase);
    float4 sv = *(const float4*)(pe + (size_t)bs * 128 + 64 + dbase);
    float c[4] = {cv.x, cv.y, cv.z, cv.w};
    float s[4] = {sv.x, sv.y, sv.z, sv.w};
    float other[4];
#pragma unroll
    for (int j = 0; j < 4; j++) other[j] = __shfl_xor_sync(0xffffffffu, xn[j], 16);
    const bool low = (lane < 16);
    float out[4];
#pragma unroll
    for (int j = 0; j < 4; j++)
        out[j] = low ? (xn[j] * c[j] - other[j] * s[j])
                     : (other[j] * s[j] + xn[j] * c[j]);

    *(uint2*)(X16 + (size_t)row * 128 + lane * 4) =
        make_uint2(pkh(out[0], out[1]), pkh(out[2], out[3]));
}

#define PREP_QB (MROWS * H_ / 4)              // 16384
#define PREP_KB (MROWS * KV_ / 4)             // 8192
#define PREP_VB (MROWS * KV_ * D_ / 4 / 256)  // 4096

__global__ __launch_bounds__(128) void prep_fused(
    const float* __restrict__ q, const float* __restrict__ k,
    const float* __restrict__ v, const float* __restrict__ pe,
    const float* __restrict__ qnw, const float* __restrict__ knw,
    __half* q16, __half* k16, __half* v16)
{
    const int bid = blockIdx.x;
    const int lane = threadIdx.x & 31, wrp = threadIdx.x >> 5;
    if (bid < PREP_QB) {
        rms_rope_warp(q, pe, qnw, H_, bid * 4 + wrp, lane, q16);
    } else if (bid < PREP_QB + PREP_KB) {
        rms_rope_warp(k, pe, knw, KV_, (bid - PREP_QB) * 4 + wrp, lane, k16);
    } else {
        int i = (bid - PREP_QB - PREP_KB) * 256 + threadIdx.x;
        const float4* v4 = (const float4*)v;
        float4 a = v4[i];
        float4 b = v4[i + 128];
        cvt_single(a, v16, i);
        cvt_single(b, v16, i + 128);
    }
}

// ---------------------------------------------------------------------------
// Flash attention, all-single fp16, causal GQA.
// BR=64 (4 warps x 16 rows), BC=64, 3-stage KV ring, 2 CTAs/SM.
// ---------------------------------------------------------------------------
#define F3STR   272u
#define F3_K    0u
#define F3_V    17408u
#define F3_STG  34816u
#define FLASH4_SMEM (3 * 34816)   // 104448

__global__ __launch_bounds__(128, 2) void flash_mma(
    const __half* __restrict__ Q16, const __half* __restrict__ K16,
    const __half* __restrict__ V16, __half* __restrict__ Oa)
{
    extern __shared__ __align__(16) char smem[];
    const uint32_t sb = smem_u32(smem);
    const int tid = threadIdx.x, lane = tid & 31, w = tid >> 5;
    const int bx = gridDim.x - 1 - blockIdx.x;   // heavy diagonals first
    const int h = blockIdx.y, b = blockIdx.z, kvh = h >> 1;
    const int g = lane >> 2, tg = lane & 3;
    const int ntiles = bx + 1;                   // BC=64 tiles; >= 1

    // ---- prologue: cp.async Q (64 rows x 128 half) into stage-2 region ----
    {
        const size_t qbase = (((size_t)b * S_ + (size_t)bx * 64) * H_ + h) * D_;
        const uint32_t qdst = sb + 2u * F3_STG;
#pragma unroll
        for (int i = 0; i < 8; i++) {
            int idx = tid + i * 128;
            int r = idx >> 4, seg = idx & 15;
            size_t src = qbase + (size_t)r * (H_ * D_) + seg * 8;
            cpasync16(qdst + (uint32_t)r * F3STR + (uint32_t)seg * 16u, Q16 + src);
        }
    }
    asm volatile("cp.async.commit_group;");

    auto fillKV = [&](int stage, int kt) {
        const size_t kbase = (((size_t)b * S_ + (size_t)kt * 64) * KV_ + kvh) * D_;
        const uint32_t sdst = sb + (uint32_t)stage * F3_STG;
#pragma unroll
        for (int i = 0; i < 8; i++) {
            int idx = tid + i * 128;
            int r = idx >> 4, seg = idx & 15;
            size_t src = kbase + (size_t)r * (KV_ * D_) + seg * 8;
            uint32_t dst = sdst + (uint32_t)r * F3STR + (uint32_t)seg * 16u;
            cpasync16(dst + F3_K, K16 + src);
            cpasync16(dst + F3_V, V16 + src);
        }
        asm volatile("cp.async.commit_group;");
    };

    fillKV(0, 0);
    fillKV(1, 1);   // kt=1 rows are always in-bounds (S=2048); unused if ntiles==1

    asm volatile("cp.async.wait_group 2;");   // Q complete (own portions)
    __syncthreads();                          // all portions visible

    // ---- Q fragments -> registers (single fp16) ----
    uint32_t qf[8][4];
    {
        const uint32_t aQ = sb + 2u * F3_STG
                          + (uint32_t)(w * 16 + (lane & 15)) * F3STR
                          + (uint32_t)((lane >> 4) * 16);
#pragma unroll
        for (int kb = 0; kb < 8; kb++)
            ldsm_x4(qf[kb][0], qf[kb][1], qf[kb][2], qf[kb][3], aQ + kb * 32);
    }

    float o[16][4];
#pragma unroll
    for (int i = 0; i < 16; i++)
#pragma unroll
        for (int j = 0; j < 4; j++) o[i][j] = 0.f;
    float m0 = -1e30f, m1 = -1e30f, l0 = 0.f, l1 = 0.f;

    const int qr0 = bx * 64 + w * 16 + g;
    const float sca2 = 0.12751744f;   // log2(e)/sqrt(128)

    int cur = 0;
    for (int kt = 0; kt < ntiles; kt++) {
        if (kt + 1 < ntiles) {
            asm volatile("cp.async.wait_group 1;");
        } else {
            asm volatile("cp.async.wait_group 0;");
        }
        __syncthreads();
        if (kt + 2 < ntiles) {
            int fs = cur + 2; if (fs >= 3) fs -= 3;
            fillKV(fs, kt + 2);
        }

        if (kt * 64 <= bx * 64 + w * 16 + 15) {   // warp has unmasked work
            const uint32_t stg = sb + (uint32_t)cur * F3_STG;
            const uint32_t bK  = stg + F3_K
                               + (uint32_t)((((lane >> 4) << 3) + (lane & 7)) * F3STR)
                               + (uint32_t)(((lane >> 3) & 1) * 16);

            // ---- S = Q K^T (single fp16); 16 rows x 64 cols ----
            float sc[8][4];
#pragma unroll
            for (int i = 0; i < 8; i++)
#pragma unroll
                for (int j = 0; j < 4; j++) sc[i][j] = 0.f;

#pragma unroll
            for (int kb = 0; kb < 8; kb++) {
#pragma unroll
                for (int nt = 0; nt < 4; nt++) {
                    uint32_t k0, k1, k2, k3;
                    ldsm_x4(k0, k1, k2, k3,
                            bK + (uint32_t)(nt * 16) * F3STR + kb * 32);
                    mma_h(sc[2 * nt],     qf[kb], k0, k1);
                    mma_h(sc[2 * nt + 1], qf[kb], k2, k3);
                }
            }

            // ---- scale (log2 domain) + causal mask ----
            const bool maskt = (kt * 64 + 63 > bx * 64 + w * 16);
            const int row0 = qr0, row1 = qr0 + 8, cb = kt * 64;
#pragma unroll
            for (int nt = 0; nt < 8; nt++) {
                int c0 = cb + nt * 8 + tg * 2;
                float v0 = sc[nt][0] * sca2, v1 = sc[nt][1] * sca2;
                float v2 = sc[nt][2] * sca2, v3 = sc[nt][3] * sca2;
                if (maskt) {
                    if (c0     > row0) v0 = -1e30f;
                    if (c0 + 1 > row0) v1 = -1e30f;
                    if (c0     > row1) v2 = -1e30f;
                    if (c0 + 1 > row1) v3 = -1e30f;
                }
                sc[nt][0] = v0; sc[nt][1] = v1; sc[nt][2] = v2; sc[nt][3] = v3;
            }

            // ---- row max ----
            float mx0 = -1e30f, mx1 = -1e30f;
#pragma unroll
            for (int nt = 0; nt < 8; nt++) {
                mx0 = fmaxf(mx0, fmaxf(sc[nt][0], sc[nt][1]));
                mx1 = fmaxf(mx1, fmaxf(sc[nt][2], sc[nt][3]));
            }
            mx0 = fmaxf(mx0, __shfl_xor_sync(0xffffffffu, mx0, 1));
            mx0 = fmaxf(mx0, __shfl_xor_sync(0xffffffffu, mx0, 2));
            mx1 = fmaxf(mx1, __shfl_xor_sync(0xffffffffu, mx1, 1));
            mx1 = fmaxf(mx1, __shfl_xor_sync(0xffffffffu, mx1, 2));
            const float mn0 = fmaxf(m0, mx0), mn1 = fmaxf(m1, mx1);
            const float al0 = exp2f(m0 - mn0), al1 = exp2f(m1 - mn1);
            m0 = mn0; m1 = mn1;
#pragma unroll
            for (int nt = 0; nt < 16; nt++) {
                o[nt][0] *= al0; o[nt][1] *= al0;
                o[nt][2] *= al1; o[nt][3] *= al1;
            }

            // ---- per-slice (4 x k16): exp2 -> pack -> PV ----
            float s0 = 0.f, s1 = 0.f;
#pragma unroll
            for (int j = 0; j < 4; j++) {
                float p00 = exp2f(sc[2 * j][0] - mn0);
                float p01 = exp2f(sc[2 * j][1] - mn0);
                float p02 = exp2f(sc[2 * j][2] - mn1);
                float p03 = exp2f(sc[2 * j][3] - mn1);
                float p10 = exp2f(sc[2 * j + 1][0] - mn0);
                float p11 = exp2f(sc[2 * j + 1][1] - mn0);
                float p12 = exp2f(sc[2 * j + 1][2] - mn1);
                float p13 = exp2f(sc[2 * j + 1][3] - mn1);
                s0 += (p00 + p01) + (p10 + p11);
                s1 += (p02 + p03) + (p12 + p13);

                uint32_t ph[4];
                ph[0] = pkh(p00, p01);
                ph[1] = pkh(p02, p03);
                ph[2] = pkh(p10, p11);
                ph[3] = pkh(p12, p13);

                const uint32_t vrow = stg + F3_V
                    + (uint32_t)((j * 16 + ((lane >> 3) & 1) * 8 + (lane & 7)) * F3STR)
                    + (uint32_t)((lane >> 4) * 16);
#pragma unroll
                for (int ntp = 0; ntp < 8; ntp++) {
                    uint32_t vh0, vh1, vh2, vh3;
                    LDSM_X4_T(vh0, vh1, vh2, vh3, vrow + ntp * 32);
                    mma_h(o[2 * ntp],     ph, vh0, vh1);
                    mma_h(o[2 * ntp + 1], ph, vh2, vh3);
                }
            }
            s0 += __shfl_xor_sync(0xffffffffu, s0, 1);
            s0 += __shfl_xor_sync(0xffffffffu, s0, 2);
            s1 += __shfl_xor_sync(0xffffffffu, s1, 1);
            s1 += __shfl_xor_sync(0xffffffffu, s1, 2);
            l0 = l0 * al0 + s0;
            l1 = l1 * al1 + s1;
        }
        if (++cur == 3) cur = 0;
    }

    // ---- epilogue: normalize, store single fp16 ----
    const float i0 = 1.f / l0, i1 = 1.f / l1;
    const size_t o0 = (((size_t)b * S_ + (size_t)qr0) * H_ + h) * D_;
    const size_t o1 = o0 + (size_t)8 * (H_ * D_);
#pragma unroll
    for (int nt = 0; nt < 16; nt++) {
        const int col = nt * 8 + tg * 2;
        *(uint32_t*)&Oa[o0 + col] = pkh(o[nt][0] * i0, o[nt][1] * i0);
        *(uint32_t*)&Oa[o1 + col] = pkh(o[nt][2] * i1, o[nt][3] * i1);
    }
}

// ---------------------------------------------------------------------------
extern "C" void kernel_launch(void* const* d_in, const int* in_sizes, int n_in,
                              void* d_out, int out_size)
{
    const float* x   = (const float*)d_in[0];
    const float* pe  = (const float*)d_in[1];
    const float* q_w = (const float*)d_in[2];
    const float* k_w = (const float*)d_in[3];
    const float* v_w = (const float*)d_in[4];
    const float* o_w = (const float*)d_in[5];
    const float* qnw = (const float*)d_in[6];
    const float* knw = (const float*)d_in[7];
    float* out = (float*)d_out;

    float *q, *k, *v;
    __half *x16, *qw16, *kw16, *vw16, *ow16;
    __half *q16, *k16, *v16, *at16;
    cudaGetSymbolAddress((void**)&q,    g_q);
    cudaGetSymbolAddress((void**)&k,    g_k);
    cudaGetSymbolAddress((void**)&v,    g_v);
    cudaGetSymbolAddress((void**)&x16,  g_x16);
    cudaGetSymbolAddress((void**)&qw16, g_qw16);
    cudaGetSymbolAddress((void**)&kw16, g_kw16);
    cudaGetSymbolAddress((void**)&vw16, g_vw16);
    cudaGetSymbolAddress((void**)&ow16, g_ow16);
    cudaGetSymbolAddress((void**)&q16,  g_q16);
    cudaGetSymbolAddress((void**)&k16,  g_k16);
    cudaGetSymbolAddress((void**)&v16,  g_v16);
    cudaGetSymbolAddress((void**)&at16, g_at16);

    cudaFuncSetAttribute(gemm_fp16, cudaFuncAttributeMaxDynamicSharedMemorySize,
                         GEMM_SMEM);
    cudaFuncSetAttribute(gemm_qkv, cudaFuncAttributeMaxDynamicSharedMemorySize,
                         GEMM_SMEM);
    cudaFuncSetAttribute(flash_mma, cudaFuncAttributeMaxDynamicSharedMemorySize,
                         FLASH4_SMEM);

    // 1) fused converts: all inputs -> single fp16
    split5<<<NSPLIT_TOT / 512, 256>>>(
        (const float4*)x, (const float4*)q_w, (const float4*)k_w,
        (const float4*)v_w, (const float4*)o_w,
        x16, qw16, kw16, vw16, ow16);

    // 2) fused Q/K/V projections (fp16 mma.sync, 2 CTAs/SM)
    gemm_qkv<<<dim3(32, 32), 256, GEMM_SMEM>>>(x16, qw16, kw16, vw16,
                                               q, k, v, HID_);

    // 3) fused prep: rms+rope(Q,K -> single fp16) + convert(V)
    prep_fused<<<PREP_QB + PREP_KB + PREP_VB, 128>>>(
        q, k, v, pe, qnw, knw, q16, k16, v16);

    // 4) causal GQA flash attention (all single fp16, BC=64; 2 CTAs/SM)
    flash_mma<<<dim3(S_ / 64, H_, B_), 128, FLASH4_SMEM>>>(
        q16, k16, v16, at16);

    // 5) output projection (fp16 mma.sync, 2 CTAs/SM)
    gemm_fp16<<<dim3(16, 32), 256, GEMM_SMEM>>>(at16, ow16, out, HID_, HID_);
}